// round 1
// baseline (speedup 1.0000x reference)
#include <cuda_runtime.h>
#include <math.h>

#define Bn 4
#define DIMc 192
#define H3 576
#define HSp 128
#define NPIX 16384
#define HEADS 6
#define CPH 32

// ---- scratch (static device allocations; no runtime alloc allowed) ----
__device__ float g_P[Bn * H3 * NPIX];       // qkv conv + pooled   [b,576,128,128]
__device__ float g_D[Bn * H3 * NPIX];       // after depthwise 3x3 [b,576,128,128]
__device__ float g_O[Bn * DIMc * NPIX];     // attention out + gelu [b,192,128,128]
__device__ float g_attn[Bn * HEADS * CPH * CPH];   // raw q.k sums
__device__ float g_A[Bn * HEADS * CPH * CPH];      // combined softmax matrix
__device__ float g_normsq[Bn * 2 * DIMc];          // ||q_c||^2, ||k_c||^2

// ---------------------------------------------------------------- zero
__global__ void k_zero() {
    int i = blockIdx.x * blockDim.x + threadIdx.x;
    if (i < Bn * HEADS * CPH * CPH) g_attn[i] = 0.f;
    if (i < Bn * 2 * DIMc)          g_normsq[i] = 0.f;
}

// ------------------------------------------- 1x1 qkv conv + 2x2 maxpool
// GEMM C[576, 262144] = W[576,192] @ x[192, 262144], fused 2x2 max.
// Block tile: 64 oc x 32 half-pixels (=128 full-res pixels), K-chunks of 32.
__global__ void __launch_bounds__(256) k_qkvpool(const float* __restrict__ x,
                                                 const float* __restrict__ w) {
    __shared__ float Xs[32 * 128];   // [k][r*64+c]
    __shared__ float Ws[32 * 72];    // [k][oc], padded

    int tid = threadIdx.x;
    int tx = tid & 31, ty = tid >> 5;
    int b   = blockIdx.z;
    int oc0 = blockIdx.y * 64;
    int hp0 = blockIdx.x * 32;          // 32 half-pixels, never crosses a row
    int hy  = hp0 >> 7;
    int wx0 = hp0 & 127;
    int r0 = hy * 2, c0 = wx0 * 2;
    const float* xb = x + (size_t)b * DIMc * 65536;

    float acc[8][4];
#pragma unroll
    for (int i = 0; i < 8; i++)
#pragma unroll
        for (int s = 0; s < 4; s++) acc[i][s] = 0.f;

    for (int k0 = 0; k0 < DIMc; k0 += 32) {
        // X chunk: 32k x 2rows x 64cols = 1024 float4
#pragma unroll
        for (int it = 0; it < 4; it++) {
            int idx = tid + it * 256;
            int k = idx >> 5, rem = idx & 31, r = rem >> 4, c4 = (rem & 15) * 4;
            float4 v = *(const float4*)(xb + ((size_t)(k0 + k) * 256 + r0 + r) * 256 + c0 + c4);
            *(float4*)(&Xs[k * 128 + r * 64 + c4]) = v;
        }
        // W chunk: 64oc x 32k, transposed into smem
#pragma unroll
        for (int it = 0; it < 2; it++) {
            int idx = tid + it * 256;
            int oc = idx >> 3, k4 = (idx & 7) * 4;
            float4 v = *(const float4*)(w + (size_t)(oc0 + oc) * DIMc + k0 + k4);
            Ws[(k4 + 0) * 72 + oc] = v.x;
            Ws[(k4 + 1) * 72 + oc] = v.y;
            Ws[(k4 + 2) * 72 + oc] = v.z;
            Ws[(k4 + 3) * 72 + oc] = v.w;
        }
        __syncthreads();
#pragma unroll
        for (int kk = 0; kk < 32; kk++) {
            float4 wa = *(const float4*)(&Ws[kk * 72 + ty * 8]);
            float4 wb = *(const float4*)(&Ws[kk * 72 + ty * 8 + 4]);
            float2 xa = *(const float2*)(&Xs[kk * 128 + 2 * tx]);
            float2 xc = *(const float2*)(&Xs[kk * 128 + 64 + 2 * tx]);
            float wv[8] = {wa.x, wa.y, wa.z, wa.w, wb.x, wb.y, wb.z, wb.w};
            float xv[4] = {xa.x, xa.y, xc.x, xc.y};
#pragma unroll
            for (int i = 0; i < 8; i++)
#pragma unroll
                for (int s = 0; s < 4; s++)
                    acc[i][s] = fmaf(wv[i], xv[s], acc[i][s]);
        }
        __syncthreads();
    }
#pragma unroll
    for (int i = 0; i < 8; i++) {
        float m = fmaxf(fmaxf(acc[i][0], acc[i][1]), fmaxf(acc[i][2], acc[i][3]));
        g_P[((size_t)b * H3 + oc0 + ty * 8 + i) * NPIX + hy * HSp + wx0 + tx] = m;
    }
}

// ------------------------------------------------- depthwise 3x3 (SAME)
// Also accumulates sum-of-squares for q/k channels (for L2 normalize).
__global__ void __launch_bounds__(256) k_dw(const float* __restrict__ dww) {
    int tid = threadIdx.x;
    int ch = blockIdx.y, b = blockIdx.z;
    int rg = blockIdx.x;  // 16-row group
    const float* src = g_P + ((size_t)b * H3 + ch) * NPIX;
    float*       dst = g_D + ((size_t)b * H3 + ch) * NPIX;
    float wgt[9];
#pragma unroll
    for (int i = 0; i < 9; i++) wgt[i] = dww[ch * 9 + i];
    float ss = 0.f;
#pragma unroll
    for (int it = 0; it < 8; it++) {
        int p = rg * 2048 + tid + it * 256;
        int r = p >> 7, c = p & 127;
        float s = 0.f;
#pragma unroll
        for (int dr = 0; dr < 3; dr++) {
            int rr = r + dr - 1;
            if (rr < 0 || rr > 127) continue;
#pragma unroll
            for (int dc = 0; dc < 3; dc++) {
                int cc = c + dc - 1;
                if (cc < 0 || cc > 127) continue;
                s = fmaf(wgt[dr * 3 + dc], __ldg(src + rr * 128 + cc), s);
            }
        }
        dst[p] = s;
        ss = fmaf(s, s, ss);
    }
    if (ch < 2 * DIMc) {
#pragma unroll
        for (int o = 16; o > 0; o >>= 1) ss += __shfl_xor_sync(0xffffffffu, ss, o);
        __shared__ float red[8];
        if ((tid & 31) == 0) red[tid >> 5] = ss;
        __syncthreads();
        if (tid < 8) {
            float v = red[tid];
#pragma unroll
            for (int o = 4; o > 0; o >>= 1) v += __shfl_xor_sync(0xffu, v, o);
            if (tid == 0) atomicAdd(&g_normsq[b * 2 * DIMc + ch], v);
        }
    }
}

// ----------------------------------------- attn[b,h,c,d] = sum_n q k  (raw)
__global__ void __launch_bounds__(256) k_attn() {
    __shared__ float qs[32 * 65];
    __shared__ float ks[32 * 65];
    int tid = threadIdx.x;
    int bh = blockIdx.y;
    int b = bh / HEADS, h = bh - b * HEADS;
    int n0 = blockIdx.x * 1024;
    const float* qb = g_D + ((size_t)b * H3 + h * CPH) * NPIX;
    const float* kb = g_D + ((size_t)b * H3 + DIMc + h * CPH) * NPIX;
    int c = tid >> 3, dg = tid & 7;
    float acc[4] = {0.f, 0.f, 0.f, 0.f};
    for (int t = 0; t < 16; t++) {
        int n = n0 + t * 64;
#pragma unroll
        for (int it = 0; it < 2; it++) {
            int idx = tid + it * 256;
            int row = idx >> 4, n4 = (idx & 15) * 4;
            float4 q4 = *(const float4*)(qb + (size_t)row * NPIX + n + n4);
            float4 k4 = *(const float4*)(kb + (size_t)row * NPIX + n + n4);
            qs[row * 65 + n4 + 0] = q4.x; qs[row * 65 + n4 + 1] = q4.y;
            qs[row * 65 + n4 + 2] = q4.z; qs[row * 65 + n4 + 3] = q4.w;
            ks[row * 65 + n4 + 0] = k4.x; ks[row * 65 + n4 + 1] = k4.y;
            ks[row * 65 + n4 + 2] = k4.z; ks[row * 65 + n4 + 3] = k4.w;
        }
        __syncthreads();
#pragma unroll
        for (int nn = 0; nn < 64; nn++) {
            float qv = qs[c * 65 + nn];
            acc[0] = fmaf(qv, ks[(dg * 4 + 0) * 65 + nn], acc[0]);
            acc[1] = fmaf(qv, ks[(dg * 4 + 1) * 65 + nn], acc[1]);
            acc[2] = fmaf(qv, ks[(dg * 4 + 2) * 65 + nn], acc[2]);
            acc[3] = fmaf(qv, ks[(dg * 4 + 3) * 65 + nn], acc[3]);
        }
        __syncthreads();
    }
#pragma unroll
    for (int j = 0; j < 4; j++)
        atomicAdd(&g_attn[((size_t)bh * CPH + c) * CPH + dg * 4 + j], acc[j]);
}

// --------------- normalize, temperature, 4x top-k masked softmax, combine
__global__ void __launch_bounds__(256) k_soft(const float* __restrict__ temp,
                                              const float* __restrict__ a1,
                                              const float* __restrict__ a2,
                                              const float* __restrict__ a3,
                                              const float* __restrict__ a4) {
    int lane = threadIdx.x & 31;
    int wid = blockIdx.x * 8 + (threadIdx.x >> 5);  // 768 warps: (bh, c)
    int bh = wid >> 5, c = wid & 31;
    int b = bh / HEADS, h = bh - b * HEADS;
    float v = g_attn[((size_t)bh * CPH + c) * CPH + lane];
    float nq = fmaxf(sqrtf(g_normsq[b * 2 * DIMc + h * CPH + c]), 1e-12f);
    float nk = fmaxf(sqrtf(g_normsq[b * 2 * DIMc + DIMc + h * CPH + lane]), 1e-12f);
    v = v / (nq * nk) * temp[h];
    // rank with top_k tie-break (lower index wins)
    int rank = 0;
#pragma unroll
    for (int j = 0; j < 32; j++) {
        float vj = __shfl_sync(0xffffffffu, v, j);
        rank += (vj > v || (vj == v && j < lane)) ? 1 : 0;
    }
    float m = v;
#pragma unroll
    for (int o = 16; o > 0; o >>= 1) m = fmaxf(m, __shfl_xor_sync(0xffffffffu, m, o));
    float e = expf(v - m);
    float e16 = rank < 16 ? e : 0.f;
    float e21 = rank < 21 ? e : 0.f;
    float e24 = rank < 24 ? e : 0.f;
    float e25 = rank < 25 ? e : 0.f;
    float s16 = e16, s21 = e21, s24 = e24, s25 = e25;
#pragma unroll
    for (int o = 16; o > 0; o >>= 1) {
        s16 += __shfl_xor_sync(0xffffffffu, s16, o);
        s21 += __shfl_xor_sync(0xffffffffu, s21, o);
        s24 += __shfl_xor_sync(0xffffffffu, s24, o);
        s25 += __shfl_xor_sync(0xffffffffu, s25, o);
    }
    float r = e16 * (a1[0] / s16) + e21 * (a2[0] / s21) +
              e24 * (a3[0] / s24) + e25 * (a4[0] / s25);
    g_A[((size_t)bh * CPH + c) * CPH + lane] = r;
}

// ---------------------------------------------- out = A @ v, exact gelu
__global__ void __launch_bounds__(256) k_av() {
    __shared__ float sA[1024];
    int tid = threadIdx.x;
    int bh = blockIdx.y;
    int b = bh / HEADS, h = bh - b * HEADS;
#pragma unroll
    for (int it = 0; it < 4; it++)
        sA[tid + it * 256] = g_A[(size_t)bh * 1024 + tid + it * 256];
    __syncthreads();
    int n = blockIdx.x * 256 + tid;
    const float* vb = g_D + ((size_t)b * H3 + 2 * DIMc + h * CPH) * NPIX + n;
    float vv[32];
#pragma unroll
    for (int d = 0; d < 32; d++) vv[d] = vb[(size_t)d * NPIX];
    float* ob = g_O + ((size_t)b * DIMc + h * CPH) * NPIX + n;
#pragma unroll
    for (int c2 = 0; c2 < 32; c2++) {
        float s = 0.f;
#pragma unroll
        for (int d = 0; d < 32; d++) s = fmaf(sA[c2 * 32 + d], vv[d], s);
        s = s * normcdff(s);   // exact gelu: x * Phi(x)
        ob[(size_t)c2 * NPIX] = s;
    }
}

// -------------------- proj 1x1 at half-res + nearest 2x upsample on write
__global__ void __launch_bounds__(256) k_proj(const float* __restrict__ w,
                                              float* __restrict__ out) {
    __shared__ float Xs[32 * 128];
    __shared__ float Ws[32 * 72];
    int tid = threadIdx.x;
    int tx = tid & 31, ty = tid >> 5;
    int b = blockIdx.z;
    int oc0 = blockIdx.y * 64;
    int n0 = blockIdx.x * 128;   // one half-res row
    float acc[8][4];
#pragma unroll
    for (int i = 0; i < 8; i++)
#pragma unroll
        for (int s = 0; s < 4; s++) acc[i][s] = 0.f;

    for (int k0 = 0; k0 < DIMc; k0 += 32) {
#pragma unroll
        for (int it = 0; it < 4; it++) {
            int idx = tid + it * 256;
            int k = idx >> 5, c4 = (idx & 31) * 4;
            *(float4*)(&Xs[k * 128 + c4]) =
                *(const float4*)(g_O + ((size_t)b * DIMc + k0 + k) * NPIX + n0 + c4);
        }
#pragma unroll
        for (int it = 0; it < 2; it++) {
            int idx = tid + it * 256;
            int oc = idx >> 3, k4 = (idx & 7) * 4;
            float4 v = *(const float4*)(w + (size_t)(oc0 + oc) * DIMc + k0 + k4);
            Ws[(k4 + 0) * 72 + oc] = v.x;
            Ws[(k4 + 1) * 72 + oc] = v.y;
            Ws[(k4 + 2) * 72 + oc] = v.z;
            Ws[(k4 + 3) * 72 + oc] = v.w;
        }
        __syncthreads();
#pragma unroll
        for (int kk = 0; kk < 32; kk++) {
            float4 wa = *(const float4*)(&Ws[kk * 72 + ty * 8]);
            float4 wb = *(const float4*)(&Ws[kk * 72 + ty * 8 + 4]);
            float wv[8] = {wa.x, wa.y, wa.z, wa.w, wb.x, wb.y, wb.z, wb.w};
            float xv[4];
#pragma unroll
            for (int s = 0; s < 4; s++) xv[s] = Xs[kk * 128 + s * 32 + tx];
#pragma unroll
            for (int i = 0; i < 8; i++)
#pragma unroll
                for (int s = 0; s < 4; s++)
                    acc[i][s] = fmaf(wv[i], xv[s], acc[i][s]);
        }
        __syncthreads();
    }
    int hy = n0 >> 7;
#pragma unroll
    for (int i = 0; i < 8; i++) {
        int oc = oc0 + ty * 8 + i;
        float* ob = out + ((size_t)b * DIMc + oc) * 65536 + (2 * hy) * 256;
#pragma unroll
        for (int s = 0; s < 4; s++) {
            int cc = s * 32 + tx;
            float vv = acc[i][s];
            float2 v2 = make_float2(vv, vv);
            *(float2*)(ob + 2 * cc) = v2;
            *(float2*)(ob + 256 + 2 * cc) = v2;
        }
    }
}

// ---------------------------------------------------------------- launch
extern "C" void kernel_launch(void* const* d_in, const int* in_sizes, int n_in,
                              void* d_out, int out_size) {
    const float* x      = (const float*)d_in[0];
    const float* temp   = (const float*)d_in[1];
    const float* qkv_w  = (const float*)d_in[2];
    const float* dw_w   = (const float*)d_in[3];
    const float* proj_w = (const float*)d_in[4];
    const float* a1 = (const float*)d_in[5];
    const float* a2 = (const float*)d_in[6];
    const float* a3 = (const float*)d_in[7];
    const float* a4 = (const float*)d_in[8];
    float* out = (float*)d_out;

    k_zero<<<96, 256>>>();
    k_qkvpool<<<dim3(512, 9, 4), 256>>>(x, qkv_w);
    k_dw<<<dim3(8, 576, 4), 256>>>(dw_w);
    k_attn<<<dim3(16, 24), 256>>>();
    k_soft<<<96, 256>>>(temp, a1, a2, a3, a4);
    k_av<<<dim3(64, 24), 256>>>();
    k_proj<<<dim3(128, 3, 4), 256>>>(proj_w, out);
}

// round 2
// speedup vs baseline: 1.0610x; 1.0610x over previous
#include <cuda_runtime.h>
#include <math.h>

#define Bn 4
#define DIMc 192
#define H3 576
#define HSp 128
#define NPIX 16384
#define HEADS 6
#define CPH 32

typedef unsigned long long u64;

// packed fp32x2 FMA (FFMA2) — PTX-only pattern, 2x fp32 throughput on sm_103a
#define FMA2(acc, a, b) \
    asm("fma.rn.f32x2 %0, %1, %2, %0;" : "+l"(acc) : "l"(a), "l"(b))
#define PACKDUP(d, x) \
    asm("mov.b64 %0, {%1, %1};" : "=l"(d) : "f"(x))
#define PACK2(d, lo, hi) \
    asm("mov.b64 %0, {%1, %2};" : "=l"(d) : "f"(lo), "f"(hi))
#define UNPACK2(lo, hi, v) \
    asm("mov.b64 {%0, %1}, %2;" : "=f"(lo), "=f"(hi) : "l"(v))

// ---- scratch (static device allocations; no runtime alloc allowed) ----
__device__ float g_P[Bn * H3 * NPIX];       // qkv conv + pooled   [b,576,128,128]
__device__ float g_D[Bn * H3 * NPIX];       // after depthwise 3x3 [b,576,128,128]
__device__ float g_O[Bn * DIMc * NPIX];     // attention out + gelu [b,192,128,128]
__device__ float g_attn[Bn * HEADS * CPH * CPH];   // raw q.k sums
__device__ float g_A[Bn * HEADS * CPH * CPH];      // combined softmax matrix
__device__ float g_normsq[Bn * 2 * DIMc];          // ||q_c||^2, ||k_c||^2

// ---------------------------------------------------------------- zero
__global__ void k_zero() {
    int i = blockIdx.x * blockDim.x + threadIdx.x;
    if (i < Bn * HEADS * CPH * CPH) g_attn[i] = 0.f;
    if (i < Bn * 2 * DIMc)          g_normsq[i] = 0.f;
}

// ------------------------------------------- 1x1 qkv conv + 2x2 maxpool
// GEMM C[576, 262144] = W[576,192] @ x[192, 262144], fused 2x2 max.
// FFMA2 inner loop: acc pairs over oc, X duplicated into both lanes.
__global__ void __launch_bounds__(256) k_qkvpool(const float* __restrict__ x,
                                                 const float* __restrict__ w) {
    __shared__ float Xs[32 * 128];   // [k][r*64+c]
    __shared__ float Ws[32 * 72];    // [k][oc], padded (even pad keeps u64 align)

    int tid = threadIdx.x;
    int tx = tid & 31, ty = tid >> 5;
    int b   = blockIdx.z;
    int oc0 = blockIdx.y * 64;
    int hp0 = blockIdx.x * 32;          // 32 half-pixels, never crosses a row
    int hy  = hp0 >> 7;
    int wx0 = hp0 & 127;
    int r0 = hy * 2, c0 = wx0 * 2;
    const float* xb = x + (size_t)b * DIMc * 65536;

    u64 acc2[4][4];   // [oc-pair][pool-pos]
#pragma unroll
    for (int p = 0; p < 4; p++)
#pragma unroll
        for (int s = 0; s < 4; s++) acc2[p][s] = 0ull;

    for (int k0 = 0; k0 < DIMc; k0 += 32) {
        // X chunk: 32k x 2rows x 64cols = 1024 float4
#pragma unroll
        for (int it = 0; it < 4; it++) {
            int idx = tid + it * 256;
            int k = idx >> 5, rem = idx & 31, r = rem >> 4, c4 = (rem & 15) * 4;
            float4 v = *(const float4*)(xb + ((size_t)(k0 + k) * 256 + r0 + r) * 256 + c0 + c4);
            *(float4*)(&Xs[k * 128 + r * 64 + c4]) = v;
        }
        // W chunk: 64oc x 32k, transposed into smem
#pragma unroll
        for (int it = 0; it < 2; it++) {
            int idx = tid + it * 256;
            int oc = idx >> 3, k4 = (idx & 7) * 4;
            float4 v = *(const float4*)(w + (size_t)(oc0 + oc) * DIMc + k0 + k4);
            Ws[(k4 + 0) * 72 + oc] = v.x;
            Ws[(k4 + 1) * 72 + oc] = v.y;
            Ws[(k4 + 2) * 72 + oc] = v.z;
            Ws[(k4 + 3) * 72 + oc] = v.w;
        }
        __syncthreads();
#pragma unroll
        for (int kk = 0; kk < 32; kk++) {
            const u64* wp = (const u64*)(&Ws[kk * 72 + ty * 8]);  // 4 oc-pairs (broadcast)
            u64 w2[4] = {wp[0], wp[1], wp[2], wp[3]};
            float2 xa = *(const float2*)(&Xs[kk * 128 + 2 * tx]);
            float2 xc = *(const float2*)(&Xs[kk * 128 + 64 + 2 * tx]);
            u64 xd[4];
            PACKDUP(xd[0], xa.x); PACKDUP(xd[1], xa.y);
            PACKDUP(xd[2], xc.x); PACKDUP(xd[3], xc.y);
#pragma unroll
            for (int p = 0; p < 4; p++)
#pragma unroll
                for (int s = 0; s < 4; s++)
                    FMA2(acc2[p][s], w2[p], xd[s]);
        }
        __syncthreads();
    }
#pragma unroll
    for (int p = 0; p < 4; p++) {
        float lo[4], hi[4];
#pragma unroll
        for (int s = 0; s < 4; s++) UNPACK2(lo[s], hi[s], acc2[p][s]);
        float mlo = fmaxf(fmaxf(lo[0], lo[1]), fmaxf(lo[2], lo[3]));
        float mhi = fmaxf(fmaxf(hi[0], hi[1]), fmaxf(hi[2], hi[3]));
        size_t base = ((size_t)b * H3 + oc0 + ty * 8 + 2 * p) * NPIX + hy * HSp + wx0 + tx;
        g_P[base] = mlo;
        g_P[base + NPIX] = mhi;
    }
}

// ------------------------------------------------- depthwise 3x3 (SAME)
__global__ void __launch_bounds__(256) k_dw(const float* __restrict__ dww) {
    int tid = threadIdx.x;
    int ch = blockIdx.y, b = blockIdx.z;
    int rg = blockIdx.x;  // 16-row group
    const float* src = g_P + ((size_t)b * H3 + ch) * NPIX;
    float*       dst = g_D + ((size_t)b * H3 + ch) * NPIX;
    float wgt[9];
#pragma unroll
    for (int i = 0; i < 9; i++) wgt[i] = dww[ch * 9 + i];
    float ss = 0.f;
#pragma unroll
    for (int it = 0; it < 8; it++) {
        int p = rg * 2048 + tid + it * 256;
        int r = p >> 7, c = p & 127;
        float s = 0.f;
#pragma unroll
        for (int dr = 0; dr < 3; dr++) {
            int rr = r + dr - 1;
            if (rr < 0 || rr > 127) continue;
#pragma unroll
            for (int dc = 0; dc < 3; dc++) {
                int cc = c + dc - 1;
                if (cc < 0 || cc > 127) continue;
                s = fmaf(wgt[dr * 3 + dc], __ldg(src + rr * 128 + cc), s);
            }
        }
        dst[p] = s;
        ss = fmaf(s, s, ss);
    }
    if (ch < 2 * DIMc) {
#pragma unroll
        for (int o = 16; o > 0; o >>= 1) ss += __shfl_xor_sync(0xffffffffu, ss, o);
        __shared__ float red[8];
        if ((tid & 31) == 0) red[tid >> 5] = ss;
        __syncthreads();
        if (tid < 8) {
            float v = red[tid];
#pragma unroll
            for (int o = 4; o > 0; o >>= 1) v += __shfl_xor_sync(0xffu, v, o);
            if (tid == 0) atomicAdd(&g_normsq[b * 2 * DIMc + ch], v);
        }
    }
}

// ----------------------------------------- attn[b,h,c,d] = sum_n q k  (raw)
// more blocks (1536) for occupancy; n-chunk = 256
__global__ void __launch_bounds__(256) k_attn() {
    __shared__ float qs[32 * 65];
    __shared__ float ks[32 * 65];
    int tid = threadIdx.x;
    int bh = blockIdx.y;
    int b = bh / HEADS, h = bh - b * HEADS;
    int n0 = blockIdx.x * 256;
    const float* qb = g_D + ((size_t)b * H3 + h * CPH) * NPIX;
    const float* kb = g_D + ((size_t)b * H3 + DIMc + h * CPH) * NPIX;
    int c = tid >> 3, dg = tid & 7;
    float acc[4] = {0.f, 0.f, 0.f, 0.f};
    for (int t = 0; t < 4; t++) {
        int n = n0 + t * 64;
#pragma unroll
        for (int it = 0; it < 2; it++) {
            int idx = tid + it * 256;
            int row = idx >> 4, n4 = (idx & 15) * 4;
            float4 q4 = *(const float4*)(qb + (size_t)row * NPIX + n + n4);
            float4 k4 = *(const float4*)(kb + (size_t)row * NPIX + n + n4);
            qs[row * 65 + n4 + 0] = q4.x; qs[row * 65 + n4 + 1] = q4.y;
            qs[row * 65 + n4 + 2] = q4.z; qs[row * 65 + n4 + 3] = q4.w;
            ks[row * 65 + n4 + 0] = k4.x; ks[row * 65 + n4 + 1] = k4.y;
            ks[row * 65 + n4 + 2] = k4.z; ks[row * 65 + n4 + 3] = k4.w;
        }
        __syncthreads();
#pragma unroll
        for (int nn = 0; nn < 64; nn++) {
            float qv = qs[c * 65 + nn];
            acc[0] = fmaf(qv, ks[(dg * 4 + 0) * 65 + nn], acc[0]);
            acc[1] = fmaf(qv, ks[(dg * 4 + 1) * 65 + nn], acc[1]);
            acc[2] = fmaf(qv, ks[(dg * 4 + 2) * 65 + nn], acc[2]);
            acc[3] = fmaf(qv, ks[(dg * 4 + 3) * 65 + nn], acc[3]);
        }
        __syncthreads();
    }
#pragma unroll
    for (int j = 0; j < 4; j++)
        atomicAdd(&g_attn[((size_t)bh * CPH + c) * CPH + dg * 4 + j], acc[j]);
}

// --------------- normalize, temperature, 4x top-k masked softmax, combine
__global__ void __launch_bounds__(256) k_soft(const float* __restrict__ temp,
                                              const float* __restrict__ a1,
                                              const float* __restrict__ a2,
                                              const float* __restrict__ a3,
                                              const float* __restrict__ a4) {
    int lane = threadIdx.x & 31;
    int wid = blockIdx.x * 8 + (threadIdx.x >> 5);  // 768 warps: (bh, c)
    int bh = wid >> 5, c = wid & 31;
    int b = bh / HEADS, h = bh - b * HEADS;
    float v = g_attn[((size_t)bh * CPH + c) * CPH + lane];
    float nq = fmaxf(sqrtf(g_normsq[b * 2 * DIMc + h * CPH + c]), 1e-12f);
    float nk = fmaxf(sqrtf(g_normsq[b * 2 * DIMc + DIMc + h * CPH + lane]), 1e-12f);
    v = v / (nq * nk) * temp[h];
    int rank = 0;
#pragma unroll
    for (int j = 0; j < 32; j++) {
        float vj = __shfl_sync(0xffffffffu, v, j);
        rank += (vj > v || (vj == v && j < lane)) ? 1 : 0;
    }
    float m = v;
#pragma unroll
    for (int o = 16; o > 0; o >>= 1) m = fmaxf(m, __shfl_xor_sync(0xffffffffu, m, o));
    float e = expf(v - m);
    float e16 = rank < 16 ? e : 0.f;
    float e21 = rank < 21 ? e : 0.f;
    float e24 = rank < 24 ? e : 0.f;
    float e25 = rank < 25 ? e : 0.f;
    float s16 = e16, s21 = e21, s24 = e24, s25 = e25;
#pragma unroll
    for (int o = 16; o > 0; o >>= 1) {
        s16 += __shfl_xor_sync(0xffffffffu, s16, o);
        s21 += __shfl_xor_sync(0xffffffffu, s21, o);
        s24 += __shfl_xor_sync(0xffffffffu, s24, o);
        s25 += __shfl_xor_sync(0xffffffffu, s25, o);
    }
    float r = e16 * (a1[0] / s16) + e21 * (a2[0] / s21) +
              e24 * (a3[0] / s24) + e25 * (a4[0] / s25);
    g_A[((size_t)bh * CPH + c) * CPH + lane] = r;
}

// ---------------------------------------------- out = A @ v, exact gelu
__global__ void __launch_bounds__(256) k_av() {
    __shared__ float sA[1024];
    int tid = threadIdx.x;
    int bh = blockIdx.y;
    int b = bh / HEADS, h = bh - b * HEADS;
#pragma unroll
    for (int it = 0; it < 4; it++)
        sA[tid + it * 256] = g_A[(size_t)bh * 1024 + tid + it * 256];
    __syncthreads();
    int n = blockIdx.x * 256 + tid;
    const float* vb = g_D + ((size_t)b * H3 + 2 * DIMc + h * CPH) * NPIX + n;
    u64 vp[16];
#pragma unroll
    for (int d = 0; d < 16; d++) {
        float v0 = vb[(size_t)(2 * d) * NPIX];
        float v1 = vb[(size_t)(2 * d + 1) * NPIX];
        PACK2(vp[d], v0, v1);
    }
    float* ob = g_O + ((size_t)b * DIMc + h * CPH) * NPIX + n;
#pragma unroll
    for (int c2 = 0; c2 < 32; c2++) {
        u64 acc = 0ull;
        const u64* ap = (const u64*)(&sA[c2 * 32]);   // broadcast pairs
#pragma unroll
        for (int d = 0; d < 16; d++)
            FMA2(acc, ap[d], vp[d]);
        float lo, hi;
        UNPACK2(lo, hi, acc);
        float s = lo + hi;
        s = s * normcdff(s);   // exact gelu: x * Phi(x)
        ob[(size_t)c2 * NPIX] = s;
    }
}

// -------------------- proj 1x1 at half-res + nearest 2x upsample on write
__global__ void __launch_bounds__(256) k_proj(const float* __restrict__ w,
                                              float* __restrict__ out) {
    __shared__ float Xs[32 * 128];
    __shared__ float Ws[32 * 72];
    int tid = threadIdx.x;
    int tx = tid & 31, ty = tid >> 5;
    int b = blockIdx.z;
    int oc0 = blockIdx.y * 64;
    int n0 = blockIdx.x * 128;   // one half-res row
    u64 acc2[4][4];
#pragma unroll
    for (int p = 0; p < 4; p++)
#pragma unroll
        for (int s = 0; s < 4; s++) acc2[p][s] = 0ull;

    for (int k0 = 0; k0 < DIMc; k0 += 32) {
#pragma unroll
        for (int it = 0; it < 4; it++) {
            int idx = tid + it * 256;
            int k = idx >> 5, c4 = (idx & 31) * 4;
            *(float4*)(&Xs[k * 128 + c4]) =
                *(const float4*)(g_O + ((size_t)b * DIMc + k0 + k) * NPIX + n0 + c4);
        }
#pragma unroll
        for (int it = 0; it < 2; it++) {
            int idx = tid + it * 256;
            int oc = idx >> 3, k4 = (idx & 7) * 4;
            float4 v = *(const float4*)(w + (size_t)(oc0 + oc) * DIMc + k0 + k4);
            Ws[(k4 + 0) * 72 + oc] = v.x;
            Ws[(k4 + 1) * 72 + oc] = v.y;
            Ws[(k4 + 2) * 72 + oc] = v.z;
            Ws[(k4 + 3) * 72 + oc] = v.w;
        }
        __syncthreads();
#pragma unroll
        for (int kk = 0; kk < 32; kk++) {
            const u64* wp = (const u64*)(&Ws[kk * 72 + ty * 8]);
            u64 w2[4] = {wp[0], wp[1], wp[2], wp[3]};
            u64 xd[4];
#pragma unroll
            for (int s = 0; s < 4; s++) {
                float xv = Xs[kk * 128 + s * 32 + tx];
                PACKDUP(xd[s], xv);
            }
#pragma unroll
            for (int p = 0; p < 4; p++)
#pragma unroll
                for (int s = 0; s < 4; s++)
                    FMA2(acc2[p][s], w2[p], xd[s]);
        }
        __syncthreads();
    }
    int hy = n0 >> 7;
#pragma unroll
    for (int p = 0; p < 4; p++) {
        float lo[4], hi[4];
#pragma unroll
        for (int s = 0; s < 4; s++) UNPACK2(lo[s], hi[s], acc2[p][s]);
#pragma unroll
        for (int half = 0; half < 2; half++) {
            int oc = oc0 + ty * 8 + 2 * p + half;
            float* ob = out + ((size_t)b * DIMc + oc) * 65536 + (2 * hy) * 256;
#pragma unroll
            for (int s = 0; s < 4; s++) {
                int cc = s * 32 + tx;
                float vv = half ? hi[s] : lo[s];
                float2 v2 = make_float2(vv, vv);
                *(float2*)(ob + 2 * cc) = v2;
                *(float2*)(ob + 256 + 2 * cc) = v2;
            }
        }
    }
}

// ---------------------------------------------------------------- launch
extern "C" void kernel_launch(void* const* d_in, const int* in_sizes, int n_in,
                              void* d_out, int out_size) {
    const float* x      = (const float*)d_in[0];
    const float* temp   = (const float*)d_in[1];
    const float* qkv_w  = (const float*)d_in[2];
    const float* dw_w   = (const float*)d_in[3];
    const float* proj_w = (const float*)d_in[4];
    const float* a1 = (const float*)d_in[5];
    const float* a2 = (const float*)d_in[6];
    const float* a3 = (const float*)d_in[7];
    const float* a4 = (const float*)d_in[8];
    float* out = (float*)d_out;

    k_zero<<<96, 256>>>();
    k_qkvpool<<<dim3(512, 9, 4), 256>>>(x, qkv_w);
    k_dw<<<dim3(8, 576, 4), 256>>>(dw_w);
    k_attn<<<dim3(64, 24), 256>>>();
    k_soft<<<96, 256>>>(temp, a1, a2, a3, a4);
    k_av<<<dim3(64, 24), 256>>>();
    k_proj<<<dim3(128, 3, 4), 256>>>(proj_w, out);
}

// round 3
// speedup vs baseline: 1.5102x; 1.4234x over previous
#include <cuda_runtime.h>
#include <cuda_bf16.h>
#include <math.h>

#define Bn 4
#define DIMc 192
#define H3 576
#define HSp 128
#define NPIX 16384
#define HEADS 6
#define CPH 32

typedef unsigned long long u64;

// packed fp32x2 FMA (kept for the small GEMMs)
#define FMA2(acc, a, b) \
    asm("fma.rn.f32x2 %0, %1, %2, %0;" : "+l"(acc) : "l"(a), "l"(b))
#define PACKDUP(d, x) \
    asm("mov.b64 %0, {%1, %1};" : "=l"(d) : "f"(x))
#define PACK2(d, lo, hi) \
    asm("mov.b64 %0, {%1, %2};" : "=l"(d) : "f"(lo), "f"(hi))
#define UNPACK2(lo, hi, v) \
    asm("mov.b64 {%0, %1}, %2;" : "=f"(lo), "=f"(hi) : "l"(v))

// ---- tensor-core helpers (legacy mma.sync path, bf16) ----
#define LDM_X4(R, addr) \
    asm volatile("ldmatrix.sync.aligned.m8n8.x4.shared.b16 {%0,%1,%2,%3}, [%4];" \
                 : "=r"((R)[0]), "=r"((R)[1]), "=r"((R)[2]), "=r"((R)[3]) : "r"(addr))
#define LDM_X4T(R, addr) \
    asm volatile("ldmatrix.sync.aligned.m8n8.x4.trans.shared.b16 {%0,%1,%2,%3}, [%4];" \
                 : "=r"((R)[0]), "=r"((R)[1]), "=r"((R)[2]), "=r"((R)[3]) : "r"(addr))
#define MMA_BF16(C, A, b0, b1) \
    asm volatile("mma.sync.aligned.m16n8k16.row.col.f32.bf16.bf16.f32 " \
                 "{%0,%1,%2,%3},{%4,%5,%6,%7},{%8,%9},{%0,%1,%2,%3};" \
                 : "+f"((C)[0]), "+f"((C)[1]), "+f"((C)[2]), "+f"((C)[3]) \
                 : "r"((A)[0]), "r"((A)[1]), "r"((A)[2]), "r"((A)[3]), "r"(b0), "r"(b1))

// ---- scratch ----
__device__ float g_P[Bn * H3 * NPIX];       // qkv conv + pooled   [b,576,128,128]
__device__ float g_D[Bn * H3 * NPIX];       // after depthwise 3x3
__device__ float g_O[Bn * DIMc * NPIX];     // attention out + gelu
__device__ float g_attn[Bn * HEADS * CPH * CPH];
__device__ float g_A[Bn * HEADS * CPH * CPH];
__device__ float g_normsq[Bn * 2 * DIMc];

// ---------------------------------------------------------------- zero
__global__ void k_zero() {
    int i = blockIdx.x * blockDim.x + threadIdx.x;
    if (i < Bn * HEADS * CPH * CPH) g_attn[i] = 0.f;
    if (i < Bn * 2 * DIMc)          g_normsq[i] = 0.f;
}

// ------------------------------------------- 1x1 qkv conv + 2x2 maxpool
// Tensor-core GEMM: C[64 oc][128 pix] per block, K=192, 3x bf16 split
// (Wh*Xh + Wh*Xl + Wl*Xh, fp32 accum). Pixel index n = 2*col + row so each
// 2x2 pool quad is 4 consecutive n; pooling = reg fmax + shfl_xor(1).
__global__ void __launch_bounds__(256) k_qkvpool(const float* __restrict__ x,
                                                 const float* __restrict__ w) {
    __shared__ __nv_bfloat16 XsH[32][136];
    __shared__ __nv_bfloat16 XsL[32][136];
    __shared__ __nv_bfloat16 WsH[64][40];
    __shared__ __nv_bfloat16 WsL[64][40];
    __shared__ float sPool[64][33];

    int tid = threadIdx.x;
    int b = blockIdx.z;
    int oc0 = blockIdx.x * 64;              // oc fastest -> X tiles L2-shared
    int y = blockIdx.y >> 2, cblk = blockIdx.y & 3;
    int r0 = y * 2, c0 = cblk * 64;
    const float* xb = x + (size_t)b * DIMc * 65536;

    int wid = tid >> 5, l = tid & 31;
    int wm = wid & 1, wn = wid >> 1;
    int m0 = wm * 32, n0 = wn * 32;

    // per-lane ldmatrix row/col pattern (element units)
    int arow = (l & 7) + ((l >> 3) & 1) * 8;
    int acol8 = (l >> 4) * 8;

    float c[2][4][4];
#pragma unroll
    for (int mf = 0; mf < 2; mf++)
#pragma unroll
        for (int j = 0; j < 4; j++)
#pragma unroll
            for (int q = 0; q < 4; q++) c[mf][j][q] = 0.f;

    for (int k0 = 0; k0 < DIMc; k0 += 32) {
        // X tile: 32 k x (2 rows x 64 cols) fp32 -> hi/lo bf16, n = 4*c2{+2}+r
#pragma unroll
        for (int it = 0; it < 8; it++) {
            int idx = tid + it * 256;            // 2048 float2 slots
            int k = idx >> 6, rem = idx & 63, r = rem >> 5, c2 = rem & 31;
            float2 v = *(const float2*)(xb + (size_t)(k0 + k) * 65536 +
                                        (r0 + r) * 256 + c0 + 2 * c2);
            __nv_bfloat16 h0 = __float2bfloat16(v.x);
            __nv_bfloat16 l0 = __float2bfloat16(v.x - __bfloat162float(h0));
            __nv_bfloat16 h1 = __float2bfloat16(v.y);
            __nv_bfloat16 l1 = __float2bfloat16(v.y - __bfloat162float(h1));
            XsH[k][4 * c2 + r] = h0;     XsL[k][4 * c2 + r] = l0;
            XsH[k][4 * c2 + 2 + r] = h1; XsL[k][4 * c2 + 2 + r] = l1;
        }
        // W tile: 64 oc x 32 k, row-major [oc][k]
#pragma unroll
        for (int it = 0; it < 4; it++) {
            int idx = tid + it * 256;            // 1024 float2 slots
            int oc = idx >> 4, kk = (idx & 15) * 2;
            float2 v = *(const float2*)(w + (size_t)(oc0 + oc) * DIMc + k0 + kk);
            __nv_bfloat16 h0 = __float2bfloat16(v.x);
            __nv_bfloat16 l0 = __float2bfloat16(v.x - __bfloat162float(h0));
            __nv_bfloat16 h1 = __float2bfloat16(v.y);
            __nv_bfloat16 l1 = __float2bfloat16(v.y - __bfloat162float(h1));
            WsH[oc][kk] = h0;     WsL[oc][kk] = l0;
            WsH[oc][kk + 1] = h1; WsL[oc][kk + 1] = l1;
        }
        __syncthreads();
#pragma unroll
        for (int ks = 0; ks < 2; ks++) {
            unsigned aH[2][4], aL[2][4], bH[2][4], bL[2][4];
#pragma unroll
            for (int mf = 0; mf < 2; mf++) {
                unsigned adrH = (unsigned)__cvta_generic_to_shared(
                    &WsH[m0 + mf * 16 + arow][ks * 16 + acol8]);
                LDM_X4(aH[mf], adrH);
                unsigned adrL = (unsigned)__cvta_generic_to_shared(
                    &WsL[m0 + mf * 16 + arow][ks * 16 + acol8]);
                LDM_X4(aL[mf], adrL);
            }
#pragma unroll
            for (int nb = 0; nb < 2; nb++) {
                unsigned adrH = (unsigned)__cvta_generic_to_shared(
                    &XsH[ks * 16 + arow][n0 + nb * 16 + acol8]);
                LDM_X4T(bH[nb], adrH);
                unsigned adrL = (unsigned)__cvta_generic_to_shared(
                    &XsL[ks * 16 + arow][n0 + nb * 16 + acol8]);
                LDM_X4T(bL[nb], adrL);
            }
#pragma unroll
            for (int mf = 0; mf < 2; mf++)
#pragma unroll
                for (int j = 0; j < 4; j++) {
                    unsigned bh0 = bH[j >> 1][(j & 1) * 2];
                    unsigned bh1 = bH[j >> 1][(j & 1) * 2 + 1];
                    unsigned bl0 = bL[j >> 1][(j & 1) * 2];
                    unsigned bl1 = bL[j >> 1][(j & 1) * 2 + 1];
                    MMA_BF16(c[mf][j], aH[mf], bh0, bh1);
                    MMA_BF16(c[mf][j], aH[mf], bl0, bl1);
                    MMA_BF16(c[mf][j], aL[mf], bh0, bh1);
                }
        }
        __syncthreads();
    }

    // epilogue: 2x2 pool (vert in-reg, horiz shfl), smem transpose, coalesced out
#pragma unroll
    for (int mf = 0; mf < 2; mf++)
#pragma unroll
        for (int j = 0; j < 4; j++) {
            float v01 = fmaxf(c[mf][j][0], c[mf][j][1]);
            float v23 = fmaxf(c[mf][j][2], c[mf][j][3]);
            float p01 = fmaxf(v01, __shfl_xor_sync(0xffffffffu, v01, 1));
            float p23 = fmaxf(v23, __shfl_xor_sync(0xffffffffu, v23, 1));
            if (!(l & 1)) {
                int hp = wn * 8 + j * 2 + ((l & 2) >> 1);
                int rl = m0 + mf * 16 + (l >> 2);
                sPool[rl][hp] = p01;
                sPool[rl + 8][hp] = p23;
            }
        }
    __syncthreads();
#pragma unroll
    for (int it = 0; it < 8; it++) {
        int t = tid + it * 256;
        int ocl = t >> 5, hx = t & 31;
        g_P[((size_t)b * H3 + oc0 + ocl) * NPIX + y * HSp + cblk * 32 + hx] =
            sPool[ocl][hx];
    }
}

// ------------------------------------------------- depthwise 3x3 (SAME)
__global__ void __launch_bounds__(256) k_dw(const float* __restrict__ dww) {
    int tid = threadIdx.x;
    int ch = blockIdx.y, b = blockIdx.z;
    int rg = blockIdx.x;
    const float* src = g_P + ((size_t)b * H3 + ch) * NPIX;
    float*       dst = g_D + ((size_t)b * H3 + ch) * NPIX;
    float wgt[9];
#pragma unroll
    for (int i = 0; i < 9; i++) wgt[i] = dww[ch * 9 + i];
    float ss = 0.f;
#pragma unroll
    for (int it = 0; it < 8; it++) {
        int p = rg * 2048 + tid + it * 256;
        int r = p >> 7, cc0 = p & 127;
        float s = 0.f;
#pragma unroll
        for (int dr = 0; dr < 3; dr++) {
            int rr = r + dr - 1;
            if (rr < 0 || rr > 127) continue;
#pragma unroll
            for (int dc = 0; dc < 3; dc++) {
                int cc = cc0 + dc - 1;
                if (cc < 0 || cc > 127) continue;
                s = fmaf(wgt[dr * 3 + dc], __ldg(src + rr * 128 + cc), s);
            }
        }
        dst[p] = s;
        ss = fmaf(s, s, ss);
    }
    if (ch < 2 * DIMc) {
#pragma unroll
        for (int o = 16; o > 0; o >>= 1) ss += __shfl_xor_sync(0xffffffffu, ss, o);
        __shared__ float red[8];
        if ((tid & 31) == 0) red[tid >> 5] = ss;
        __syncthreads();
        if (tid < 8) {
            float v = red[tid];
#pragma unroll
            for (int o = 4; o > 0; o >>= 1) v += __shfl_xor_sync(0xffu, v, o);
            if (tid == 0) atomicAdd(&g_normsq[b * 2 * DIMc + ch], v);
        }
    }
}

// ----------------------------------------- attn[b,h,c,d] = sum_n q k
__global__ void __launch_bounds__(256) k_attn() {
    __shared__ float qs[32 * 65];
    __shared__ float ks[32 * 65];
    int tid = threadIdx.x;
    int bh = blockIdx.y;
    int b = bh / HEADS, h = bh - b * HEADS;
    int n0 = blockIdx.x * 256;
    const float* qb = g_D + ((size_t)b * H3 + h * CPH) * NPIX;
    const float* kb = g_D + ((size_t)b * H3 + DIMc + h * CPH) * NPIX;
    int c = tid >> 3, dg = tid & 7;
    float acc[4] = {0.f, 0.f, 0.f, 0.f};
    for (int t = 0; t < 4; t++) {
        int n = n0 + t * 64;
#pragma unroll
        for (int it = 0; it < 2; it++) {
            int idx = tid + it * 256;
            int row = idx >> 4, n4 = (idx & 15) * 4;
            float4 q4 = *(const float4*)(qb + (size_t)row * NPIX + n + n4);
            float4 k4 = *(const float4*)(kb + (size_t)row * NPIX + n + n4);
            qs[row * 65 + n4 + 0] = q4.x; qs[row * 65 + n4 + 1] = q4.y;
            qs[row * 65 + n4 + 2] = q4.z; qs[row * 65 + n4 + 3] = q4.w;
            ks[row * 65 + n4 + 0] = k4.x; ks[row * 65 + n4 + 1] = k4.y;
            ks[row * 65 + n4 + 2] = k4.z; ks[row * 65 + n4 + 3] = k4.w;
        }
        __syncthreads();
#pragma unroll
        for (int nn = 0; nn < 64; nn++) {
            float qv = qs[c * 65 + nn];
            acc[0] = fmaf(qv, ks[(dg * 4 + 0) * 65 + nn], acc[0]);
            acc[1] = fmaf(qv, ks[(dg * 4 + 1) * 65 + nn], acc[1]);
            acc[2] = fmaf(qv, ks[(dg * 4 + 2) * 65 + nn], acc[2]);
            acc[3] = fmaf(qv, ks[(dg * 4 + 3) * 65 + nn], acc[3]);
        }
        __syncthreads();
    }
#pragma unroll
    for (int j = 0; j < 4; j++)
        atomicAdd(&g_attn[((size_t)bh * CPH + c) * CPH + dg * 4 + j], acc[j]);
}

// --------------- normalize, temperature, 4x top-k masked softmax, combine
__global__ void __launch_bounds__(256) k_soft(const float* __restrict__ temp,
                                              const float* __restrict__ a1,
                                              const float* __restrict__ a2,
                                              const float* __restrict__ a3,
                                              const float* __restrict__ a4) {
    int lane = threadIdx.x & 31;
    int wid = blockIdx.x * 8 + (threadIdx.x >> 5);
    int bh = wid >> 5, c = wid & 31;
    int b = bh / HEADS, h = bh - b * HEADS;
    float v = g_attn[((size_t)bh * CPH + c) * CPH + lane];
    float nq = fmaxf(sqrtf(g_normsq[b * 2 * DIMc + h * CPH + c]), 1e-12f);
    float nk = fmaxf(sqrtf(g_normsq[b * 2 * DIMc + DIMc + h * CPH + lane]), 1e-12f);
    v = v / (nq * nk) * temp[h];
    int rank = 0;
#pragma unroll
    for (int j = 0; j < 32; j++) {
        float vj = __shfl_sync(0xffffffffu, v, j);
        rank += (vj > v || (vj == v && j < lane)) ? 1 : 0;
    }
    float m = v;
#pragma unroll
    for (int o = 16; o > 0; o >>= 1) m = fmaxf(m, __shfl_xor_sync(0xffffffffu, m, o));
    float e = expf(v - m);
    float e16 = rank < 16 ? e : 0.f;
    float e21 = rank < 21 ? e : 0.f;
    float e24 = rank < 24 ? e : 0.f;
    float e25 = rank < 25 ? e : 0.f;
    float s16 = e16, s21 = e21, s24 = e24, s25 = e25;
#pragma unroll
    for (int o = 16; o > 0; o >>= 1) {
        s16 += __shfl_xor_sync(0xffffffffu, s16, o);
        s21 += __shfl_xor_sync(0xffffffffu, s21, o);
        s24 += __shfl_xor_sync(0xffffffffu, s24, o);
        s25 += __shfl_xor_sync(0xffffffffu, s25, o);
    }
    float r = e16 * (a1[0] / s16) + e21 * (a2[0] / s21) +
              e24 * (a3[0] / s24) + e25 * (a4[0] / s25);
    g_A[((size_t)bh * CPH + c) * CPH + lane] = r;
}

// ---------------------------------------------- out = A @ v, exact gelu
__global__ void __launch_bounds__(256) k_av() {
    __shared__ float sA[1024];
    int tid = threadIdx.x;
    int bh = blockIdx.y;
    int b = bh / HEADS, h = bh - b * HEADS;
#pragma unroll
    for (int it = 0; it < 4; it++)
        sA[tid + it * 256] = g_A[(size_t)bh * 1024 + tid + it * 256];
    __syncthreads();
    int n = blockIdx.x * 256 + tid;
    const float* vb = g_D + ((size_t)b * H3 + 2 * DIMc + h * CPH) * NPIX + n;
    u64 vp[16];
#pragma unroll
    for (int d = 0; d < 16; d++) {
        float v0 = vb[(size_t)(2 * d) * NPIX];
        float v1 = vb[(size_t)(2 * d + 1) * NPIX];
        PACK2(vp[d], v0, v1);
    }
    float* ob = g_O + ((size_t)b * DIMc + h * CPH) * NPIX + n;
#pragma unroll
    for (int c2 = 0; c2 < 32; c2++) {
        u64 acc = 0ull;
        const u64* ap = (const u64*)(&sA[c2 * 32]);
#pragma unroll
        for (int d = 0; d < 16; d++)
            FMA2(acc, ap[d], vp[d]);
        float lo, hi;
        UNPACK2(lo, hi, acc);
        float s = lo + hi;
        s = s * normcdff(s);
        ob[(size_t)c2 * NPIX] = s;
    }
}

// -------------------- proj 1x1 at half-res + nearest 2x upsample on write
__global__ void __launch_bounds__(256) k_proj(const float* __restrict__ w,
                                              float* __restrict__ out) {
    __shared__ float Xs[32 * 128];
    __shared__ float Ws[32 * 72];
    int tid = threadIdx.x;
    int tx = tid & 31, ty = tid >> 5;
    int b = blockIdx.z;
    int oc0 = blockIdx.y * 64;
    int n0 = blockIdx.x * 128;
    u64 acc2[4][4];
#pragma unroll
    for (int p = 0; p < 4; p++)
#pragma unroll
        for (int s = 0; s < 4; s++) acc2[p][s] = 0ull;

    for (int k0 = 0; k0 < DIMc; k0 += 32) {
#pragma unroll
        for (int it = 0; it < 4; it++) {
            int idx = tid + it * 256;
            int k = idx >> 5, c4 = (idx & 31) * 4;
            *(float4*)(&Xs[k * 128 + c4]) =
                *(const float4*)(g_O + ((size_t)b * DIMc + k0 + k) * NPIX + n0 + c4);
        }
#pragma unroll
        for (int it = 0; it < 2; it++) {
            int idx = tid + it * 256;
            int oc = idx >> 3, k4 = (idx & 7) * 4;
            float4 v = *(const float4*)(w + (size_t)(oc0 + oc) * DIMc + k0 + k4);
            Ws[(k4 + 0) * 72 + oc] = v.x;
            Ws[(k4 + 1) * 72 + oc] = v.y;
            Ws[(k4 + 2) * 72 + oc] = v.z;
            Ws[(k4 + 3) * 72 + oc] = v.w;
        }
        __syncthreads();
#pragma unroll
        for (int kk = 0; kk < 32; kk++) {
            const u64* wp = (const u64*)(&Ws[kk * 72 + ty * 8]);
            u64 w2[4] = {wp[0], wp[1], wp[2], wp[3]};
            u64 xd[4];
#pragma unroll
            for (int s = 0; s < 4; s++) {
                float xv = Xs[kk * 128 + s * 32 + tx];
                PACKDUP(xd[s], xv);
            }
#pragma unroll
            for (int p = 0; p < 4; p++)
#pragma unroll
                for (int s = 0; s < 4; s++)
                    FMA2(acc2[p][s], w2[p], xd[s]);
        }
        __syncthreads();
    }
    int hy = n0 >> 7;
#pragma unroll
    for (int p = 0; p < 4; p++) {
        float lo[4], hi[4];
#pragma unroll
        for (int s = 0; s < 4; s++) UNPACK2(lo[s], hi[s], acc2[p][s]);
#pragma unroll
        for (int half = 0; half < 2; half++) {
            int oc = oc0 + ty * 8 + 2 * p + half;
            float* ob = out + ((size_t)b * DIMc + oc) * 65536 + (2 * hy) * 256;
#pragma unroll
            for (int s = 0; s < 4; s++) {
                int cc = s * 32 + tx;
                float vv = half ? hi[s] : lo[s];
                float2 v2 = make_float2(vv, vv);
                *(float2*)(ob + 2 * cc) = v2;
                *(float2*)(ob + 256 + 2 * cc) = v2;
            }
        }
    }
}

// ---------------------------------------------------------------- launch
extern "C" void kernel_launch(void* const* d_in, const int* in_sizes, int n_in,
                              void* d_out, int out_size) {
    const float* x      = (const float*)d_in[0];
    const float* temp   = (const float*)d_in[1];
    const float* qkv_w  = (const float*)d_in[2];
    const float* dw_w   = (const float*)d_in[3];
    const float* proj_w = (const float*)d_in[4];
    const float* a1 = (const float*)d_in[5];
    const float* a2 = (const float*)d_in[6];
    const float* a3 = (const float*)d_in[7];
    const float* a4 = (const float*)d_in[8];
    float* out = (float*)d_out;

    k_zero<<<96, 256>>>();
    k_qkvpool<<<dim3(9, 512, 4), 256>>>(x, qkv_w);
    k_dw<<<dim3(8, 576, 4), 256>>>(dw_w);
    k_attn<<<dim3(64, 24), 256>>>();
    k_soft<<<96, 256>>>(temp, a1, a2, a3, a4);
    k_av<<<dim3(64, 24), 256>>>();
    k_proj<<<dim3(128, 3, 4), 256>>>(proj_w, out);
}

// round 4
// speedup vs baseline: 1.7728x; 1.1739x over previous
#include <cuda_runtime.h>
#include <cuda_bf16.h>
#include <math.h>

#define Bn 4
#define DIMc 192
#define H3 576
#define HSp 128
#define NPIX 16384
#define HEADS 6
#define CPH 32

typedef unsigned long long u64;

#define FMA2(acc, a, b) \
    asm("fma.rn.f32x2 %0, %1, %2, %0;" : "+l"(acc) : "l"(a), "l"(b))
#define PACKDUP(d, x) \
    asm("mov.b64 %0, {%1, %1};" : "=l"(d) : "f"(x))
#define PACK2(d, lo, hi) \
    asm("mov.b64 %0, {%1, %2};" : "=l"(d) : "f"(lo), "f"(hi))
#define UNPACK2(lo, hi, v) \
    asm("mov.b64 {%0, %1}, %2;" : "=f"(lo), "=f"(hi) : "l"(v))

#define LDM_X4(R, addr) \
    asm volatile("ldmatrix.sync.aligned.m8n8.x4.shared.b16 {%0,%1,%2,%3}, [%4];" \
                 : "=r"((R)[0]), "=r"((R)[1]), "=r"((R)[2]), "=r"((R)[3]) : "r"(addr))
#define LDM_X4T(R, addr) \
    asm volatile("ldmatrix.sync.aligned.m8n8.x4.trans.shared.b16 {%0,%1,%2,%3}, [%4];" \
                 : "=r"((R)[0]), "=r"((R)[1]), "=r"((R)[2]), "=r"((R)[3]) : "r"(addr))
#define MMA_BF16(C, A, b0, b1) \
    asm volatile("mma.sync.aligned.m16n8k16.row.col.f32.bf16.bf16.f32 " \
                 "{%0,%1,%2,%3},{%4,%5,%6,%7},{%8,%9},{%0,%1,%2,%3};" \
                 : "+f"((C)[0]), "+f"((C)[1]), "+f"((C)[2]), "+f"((C)[3]) \
                 : "r"((A)[0]), "r"((A)[1]), "r"((A)[2]), "r"((A)[3]), "r"(b0), "r"(b1))

// ---- scratch ----
__device__ float g_P[Bn * H3 * NPIX];
__device__ float g_D[Bn * H3 * NPIX];
__device__ float g_O[Bn * DIMc * NPIX];
__device__ float g_attn[Bn * HEADS * CPH * CPH];
__device__ float g_A[Bn * HEADS * CPH * CPH];
__device__ float g_normsq[Bn * 2 * DIMc];

// ---------------------------------------------------------------- zero
__global__ void k_zero() {
    int i = blockIdx.x * blockDim.x + threadIdx.x;
    if (i < Bn * HEADS * CPH * CPH) g_attn[i] = 0.f;
    if (i < Bn * 2 * DIMc)          g_normsq[i] = 0.f;
}

// ------------------------------------------- 1x1 qkv conv + 2x2 maxpool
// Tensor-core GEMM: C[96 oc][128 pix] per block, K=192, 3x bf16 split.
// oc-tile 96 -> only 6 blocks re-read each X tile (L2 relief).
__global__ void __launch_bounds__(256) k_qkvpool(const float* __restrict__ x,
                                                 const float* __restrict__ w) {
    __shared__ __nv_bfloat16 XsH[32][136];
    __shared__ __nv_bfloat16 XsL[32][136];
    __shared__ __nv_bfloat16 WsH[96][40];
    __shared__ __nv_bfloat16 WsL[96][40];
    __shared__ float sPool[96][33];

    int tid = threadIdx.x;
    int b = blockIdx.z;
    int oc0 = blockIdx.x * 96;              // oc fastest -> X tiles L2-shared
    int y = blockIdx.y >> 2, cblk = blockIdx.y & 3;
    int r0 = y * 2, c0 = cblk * 64;
    const float* xb = x + (size_t)b * DIMc * 65536;

    int wid = tid >> 5, l = tid & 31;
    int wm = wid & 1, wn = wid >> 1;
    int m0 = wm * 48, n0 = wn * 32;

    int arow = (l & 7) + ((l >> 3) & 1) * 8;
    int acol8 = (l >> 4) * 8;

    float c[3][4][4];
#pragma unroll
    for (int mf = 0; mf < 3; mf++)
#pragma unroll
        for (int j = 0; j < 4; j++)
#pragma unroll
            for (int q = 0; q < 4; q++) c[mf][j][q] = 0.f;

    for (int k0 = 0; k0 < DIMc; k0 += 32) {
        // X tile: 32 k x (2 rows x 64 cols) fp32 -> hi/lo bf16, n = 4*c2(+2)+r
#pragma unroll
        for (int it = 0; it < 8; it++) {
            int idx = tid + it * 256;
            int k = idx >> 6, rem = idx & 63, r = rem >> 5, c2 = rem & 31;
            float2 v = *(const float2*)(xb + (size_t)(k0 + k) * 65536 +
                                        (r0 + r) * 256 + c0 + 2 * c2);
            __nv_bfloat16 h0 = __float2bfloat16(v.x);
            __nv_bfloat16 l0 = __float2bfloat16(v.x - __bfloat162float(h0));
            __nv_bfloat16 h1 = __float2bfloat16(v.y);
            __nv_bfloat16 l1 = __float2bfloat16(v.y - __bfloat162float(h1));
            XsH[k][4 * c2 + r] = h0;     XsL[k][4 * c2 + r] = l0;
            XsH[k][4 * c2 + 2 + r] = h1; XsL[k][4 * c2 + 2 + r] = l1;
        }
        // W tile: 96 oc x 32 k
#pragma unroll
        for (int it = 0; it < 6; it++) {
            int idx = tid + it * 256;
            int oc = idx >> 4, kk = (idx & 15) * 2;
            float2 v = *(const float2*)(w + (size_t)(oc0 + oc) * DIMc + k0 + kk);
            __nv_bfloat16 h0 = __float2bfloat16(v.x);
            __nv_bfloat16 l0 = __float2bfloat16(v.x - __bfloat162float(h0));
            __nv_bfloat16 h1 = __float2bfloat16(v.y);
            __nv_bfloat16 l1 = __float2bfloat16(v.y - __bfloat162float(h1));
            WsH[oc][kk] = h0;     WsL[oc][kk] = l0;
            WsH[oc][kk + 1] = h1; WsL[oc][kk + 1] = l1;
        }
        __syncthreads();
#pragma unroll
        for (int ks = 0; ks < 2; ks++) {
            unsigned aH[3][4], aL[3][4], bH[2][4], bL[2][4];
#pragma unroll
            for (int mf = 0; mf < 3; mf++) {
                unsigned adrH = (unsigned)__cvta_generic_to_shared(
                    &WsH[m0 + mf * 16 + arow][ks * 16 + acol8]);
                LDM_X4(aH[mf], adrH);
                unsigned adrL = (unsigned)__cvta_generic_to_shared(
                    &WsL[m0 + mf * 16 + arow][ks * 16 + acol8]);
                LDM_X4(aL[mf], adrL);
            }
#pragma unroll
            for (int nb = 0; nb < 2; nb++) {
                unsigned adrH = (unsigned)__cvta_generic_to_shared(
                    &XsH[ks * 16 + arow][n0 + nb * 16 + acol8]);
                LDM_X4T(bH[nb], adrH);
                unsigned adrL = (unsigned)__cvta_generic_to_shared(
                    &XsL[ks * 16 + arow][n0 + nb * 16 + acol8]);
                LDM_X4T(bL[nb], adrL);
            }
#pragma unroll
            for (int mf = 0; mf < 3; mf++)
#pragma unroll
                for (int j = 0; j < 4; j++) {
                    unsigned bh0 = bH[j >> 1][(j & 1) * 2];
                    unsigned bh1 = bH[j >> 1][(j & 1) * 2 + 1];
                    unsigned bl0 = bL[j >> 1][(j & 1) * 2];
                    unsigned bl1 = bL[j >> 1][(j & 1) * 2 + 1];
                    MMA_BF16(c[mf][j], aH[mf], bh0, bh1);
                    MMA_BF16(c[mf][j], aH[mf], bl0, bl1);
                    MMA_BF16(c[mf][j], aL[mf], bh0, bh1);
                }
        }
        __syncthreads();
    }

    // epilogue: 2x2 pool, smem transpose, coalesced out
#pragma unroll
    for (int mf = 0; mf < 3; mf++)
#pragma unroll
        for (int j = 0; j < 4; j++) {
            float v01 = fmaxf(c[mf][j][0], c[mf][j][1]);
            float v23 = fmaxf(c[mf][j][2], c[mf][j][3]);
            float p01 = fmaxf(v01, __shfl_xor_sync(0xffffffffu, v01, 1));
            float p23 = fmaxf(v23, __shfl_xor_sync(0xffffffffu, v23, 1));
            if (!(l & 1)) {
                int hp = wn * 8 + j * 2 + ((l & 2) >> 1);
                int rl = m0 + mf * 16 + (l >> 2);
                sPool[rl][hp] = p01;
                sPool[rl + 8][hp] = p23;
            }
        }
    __syncthreads();
#pragma unroll
    for (int it = 0; it < 12; it++) {
        int t = tid + it * 256;
        int ocl = t >> 5, hx = t & 31;
        g_P[((size_t)b * H3 + oc0 + ocl) * NPIX + y * HSp + cblk * 32 + hx] =
            sPool[ocl][hx];
    }
}

// ------------------------------------------------- depthwise 3x3 (SAME)
// smem halo tile, branch-free inner loop
__global__ void __launch_bounds__(256) k_dw(const float* __restrict__ dww) {
    __shared__ float sm[18][132];
    int tid = threadIdx.x;
    int ch = blockIdx.y, b = blockIdx.z;
    int rg = blockIdx.x;                 // 16-row group
    int r0 = rg * 16;
    const float* src = g_P + ((size_t)b * H3 + ch) * NPIX;
    float*       dst = g_D + ((size_t)b * H3 + ch) * NPIX;
    float wgt[9];
#pragma unroll
    for (int i = 0; i < 9; i++) wgt[i] = dww[ch * 9 + i];

    // load 18 rows x 128 cols (+ zero side halo)
#pragma unroll
    for (int it = 0; it < 3; it++) {
        int idx = tid + it * 256;
        if (idx < 18 * 32) {
            int lr = idx >> 5, c4 = (idx & 31) * 4;
            int rr = r0 + lr - 1;
            float4 v = make_float4(0.f, 0.f, 0.f, 0.f);
            if (rr >= 0 && rr < 128)
                v = *(const float4*)(src + rr * 128 + c4);
            sm[lr][1 + c4] = v.x; sm[lr][2 + c4] = v.y;
            sm[lr][3 + c4] = v.z; sm[lr][4 + c4] = v.w;
            if (c4 == 0)  sm[lr][0] = 0.f;
            if (c4 == 124) sm[lr][129] = 0.f;
        }
    }
    __syncthreads();

    float ss = 0.f;
#pragma unroll
    for (int it = 0; it < 8; it++) {
        int p = tid + it * 256;          // 0..2047
        int r = p >> 7, cc = p & 127;
        float s = 0.f;
#pragma unroll
        for (int dr = 0; dr < 3; dr++)
#pragma unroll
            for (int dc = 0; dc < 3; dc++)
                s = fmaf(wgt[dr * 3 + dc], sm[r + dr][cc + dc], s);
        dst[r0 * 128 + p] = s;
        ss = fmaf(s, s, ss);
    }
    if (ch < 2 * DIMc) {
#pragma unroll
        for (int o = 16; o > 0; o >>= 1) ss += __shfl_xor_sync(0xffffffffu, ss, o);
        __shared__ float red[8];
        if ((tid & 31) == 0) red[tid >> 5] = ss;
        __syncthreads();
        if (tid < 8) {
            float v = red[tid];
#pragma unroll
            for (int o = 4; o > 0; o >>= 1) v += __shfl_xor_sync(0xffu, v, o);
            if (tid == 0) atomicAdd(&g_normsq[b * 2 * DIMc + ch], v);
        }
    }
}

// ----------------------------------------- attn[b,h,c,d] = sum_n q k
// register-tiled 4x4 per thread; 4 n-slices of 16 per 64-n tile
__global__ void __launch_bounds__(256) k_attn() {
    __shared__ float qs[32][65];
    __shared__ float ks[32][65];
    int tid = threadIdx.x;
    int bh = blockIdx.y;
    int b = bh / HEADS, h = bh - b * HEADS;
    int n0 = blockIdx.x * 1024;
    const float* qb = g_D + ((size_t)b * H3 + h * CPH) * NPIX;
    const float* kb = g_D + ((size_t)b * H3 + DIMc + h * CPH) * NPIX;
    int dgi = tid & 7, cg = (tid >> 3) & 7, sl = tid >> 6;
    float acc[4][4];
#pragma unroll
    for (int i = 0; i < 4; i++)
#pragma unroll
        for (int j = 0; j < 4; j++) acc[i][j] = 0.f;

    for (int t = 0; t < 16; t++) {
        int n = n0 + t * 64;
#pragma unroll
        for (int it = 0; it < 2; it++) {
            int idx = tid + it * 256;
            int row = idx >> 4, n4 = (idx & 15) * 4;
            float4 q4 = *(const float4*)(qb + (size_t)row * NPIX + n + n4);
            float4 k4 = *(const float4*)(kb + (size_t)row * NPIX + n + n4);
            qs[row][n4 + 0] = q4.x; qs[row][n4 + 1] = q4.y;
            qs[row][n4 + 2] = q4.z; qs[row][n4 + 3] = q4.w;
            ks[row][n4 + 0] = k4.x; ks[row][n4 + 1] = k4.y;
            ks[row][n4 + 2] = k4.z; ks[row][n4 + 3] = k4.w;
        }
        __syncthreads();
#pragma unroll
        for (int nn = sl * 16; nn < sl * 16 + 16; nn++) {
            float qv[4], kv[4];
#pragma unroll
            for (int i = 0; i < 4; i++) qv[i] = qs[cg * 4 + i][nn];
#pragma unroll
            for (int j = 0; j < 4; j++) kv[j] = ks[dgi * 4 + j][nn];
#pragma unroll
            for (int i = 0; i < 4; i++)
#pragma unroll
                for (int j = 0; j < 4; j++)
                    acc[i][j] = fmaf(qv[i], kv[j], acc[i][j]);
        }
        __syncthreads();
    }
#pragma unroll
    for (int i = 0; i < 4; i++)
#pragma unroll
        for (int j = 0; j < 4; j++)
            atomicAdd(&g_attn[((size_t)bh * CPH + cg * 4 + i) * CPH + dgi * 4 + j],
                      acc[i][j]);
}

// --------------- normalize, temperature, 4x top-k masked softmax, combine
__global__ void __launch_bounds__(256) k_soft(const float* __restrict__ temp,
                                              const float* __restrict__ a1,
                                              const float* __restrict__ a2,
                                              const float* __restrict__ a3,
                                              const float* __restrict__ a4) {
    int lane = threadIdx.x & 31;
    int wid = blockIdx.x * 8 + (threadIdx.x >> 5);
    int bh = wid >> 5, c = wid & 31;
    int b = bh / HEADS, h = bh - b * HEADS;
    float v = g_attn[((size_t)bh * CPH + c) * CPH + lane];
    float nq = fmaxf(sqrtf(g_normsq[b * 2 * DIMc + h * CPH + c]), 1e-12f);
    float nk = fmaxf(sqrtf(g_normsq[b * 2 * DIMc + DIMc + h * CPH + lane]), 1e-12f);
    v = v / (nq * nk) * temp[h];
    int rank = 0;
#pragma unroll
    for (int j = 0; j < 32; j++) {
        float vj = __shfl_sync(0xffffffffu, v, j);
        rank += (vj > v || (vj == v && j < lane)) ? 1 : 0;
    }
    float m = v;
#pragma unroll
    for (int o = 16; o > 0; o >>= 1) m = fmaxf(m, __shfl_xor_sync(0xffffffffu, m, o));
    float e = expf(v - m);
    float e16 = rank < 16 ? e : 0.f;
    float e21 = rank < 21 ? e : 0.f;
    float e24 = rank < 24 ? e : 0.f;
    float e25 = rank < 25 ? e : 0.f;
    float s16 = e16, s21 = e21, s24 = e24, s25 = e25;
#pragma unroll
    for (int o = 16; o > 0; o >>= 1) {
        s16 += __shfl_xor_sync(0xffffffffu, s16, o);
        s21 += __shfl_xor_sync(0xffffffffu, s21, o);
        s24 += __shfl_xor_sync(0xffffffffu, s24, o);
        s25 += __shfl_xor_sync(0xffffffffu, s25, o);
    }
    float r = e16 * (a1[0] / s16) + e21 * (a2[0] / s21) +
              e24 * (a3[0] / s24) + e25 * (a4[0] / s25);
    g_A[((size_t)bh * CPH + c) * CPH + lane] = r;
}

// ---------------------------------------------- out = A @ v, exact gelu
__global__ void __launch_bounds__(256) k_av() {
    __shared__ float sA[1024];
    int tid = threadIdx.x;
    int bh = blockIdx.y;
    int b = bh / HEADS, h = bh - b * HEADS;
#pragma unroll
    for (int it = 0; it < 4; it++)
        sA[tid + it * 256] = g_A[(size_t)bh * 1024 + tid + it * 256];
    __syncthreads();
    int n = blockIdx.x * 256 + tid;
    const float* vb = g_D + ((size_t)b * H3 + 2 * DIMc + h * CPH) * NPIX + n;
    u64 vp[16];
#pragma unroll
    for (int d = 0; d < 16; d++) {
        float v0 = vb[(size_t)(2 * d) * NPIX];
        float v1 = vb[(size_t)(2 * d + 1) * NPIX];
        PACK2(vp[d], v0, v1);
    }
    float* ob = g_O + ((size_t)b * DIMc + h * CPH) * NPIX + n;
#pragma unroll
    for (int c2 = 0; c2 < 32; c2++) {
        u64 acc = 0ull;
        const u64* ap = (const u64*)(&sA[c2 * 32]);
#pragma unroll
        for (int d = 0; d < 16; d++)
            FMA2(acc, ap[d], vp[d]);
        float lo, hi;
        UNPACK2(lo, hi, acc);
        float s = lo + hi;
        s = s * normcdff(s);
        ob[(size_t)c2 * NPIX] = s;
    }
}

// -------------------- proj 1x1 at half-res + nearest 2x upsample on write
__global__ void __launch_bounds__(256) k_proj(const float* __restrict__ w,
                                              float* __restrict__ out) {
    __shared__ float Xs[32 * 128];
    __shared__ float Ws[32 * 72];
    int tid = threadIdx.x;
    int tx = tid & 31, ty = tid >> 5;
    int b = blockIdx.z;
    int oc0 = blockIdx.y * 64;
    int n0 = blockIdx.x * 128;
    u64 acc2[4][4];
#pragma unroll
    for (int p = 0; p < 4; p++)
#pragma unroll
        for (int s = 0; s < 4; s++) acc2[p][s] = 0ull;

    for (int k0 = 0; k0 < DIMc; k0 += 32) {
#pragma unroll
        for (int it = 0; it < 4; it++) {
            int idx = tid + it * 256;
            int k = idx >> 5, c4 = (idx & 31) * 4;
            *(float4*)(&Xs[k * 128 + c4]) =
                *(const float4*)(g_O + ((size_t)b * DIMc + k0 + k) * NPIX + n0 + c4);
        }
#pragma unroll
        for (int it = 0; it < 2; it++) {
            int idx = tid + it * 256;
            int oc = idx >> 3, k4 = (idx & 7) * 4;
            float4 v = *(const float4*)(w + (size_t)(oc0 + oc) * DIMc + k0 + k4);
            Ws[(k4 + 0) * 72 + oc] = v.x;
            Ws[(k4 + 1) * 72 + oc] = v.y;
            Ws[(k4 + 2) * 72 + oc] = v.z;
            Ws[(k4 + 3) * 72 + oc] = v.w;
        }
        __syncthreads();
#pragma unroll
        for (int kk = 0; kk < 32; kk++) {
            const u64* wp = (const u64*)(&Ws[kk * 72 + ty * 8]);
            u64 w2[4] = {wp[0], wp[1], wp[2], wp[3]};
            u64 xd[4];
#pragma unroll
            for (int s = 0; s < 4; s++) {
                float xv = Xs[kk * 128 + s * 32 + tx];
                PACKDUP(xd[s], xv);
            }
#pragma unroll
            for (int p = 0; p < 4; p++)
#pragma unroll
                for (int s = 0; s < 4; s++)
                    FMA2(acc2[p][s], w2[p], xd[s]);
        }
        __syncthreads();
    }
    int hy = n0 >> 7;
#pragma unroll
    for (int p = 0; p < 4; p++) {
        float lo[4], hi[4];
#pragma unroll
        for (int s = 0; s < 4; s++) UNPACK2(lo[s], hi[s], acc2[p][s]);
#pragma unroll
        for (int half = 0; half < 2; half++) {
            int oc = oc0 + ty * 8 + 2 * p + half;
            float* ob = out + ((size_t)b * DIMc + oc) * 65536 + (2 * hy) * 256;
#pragma unroll
            for (int s = 0; s < 4; s++) {
                int cc = s * 32 + tx;
                float vv = half ? hi[s] : lo[s];
                float2 v2 = make_float2(vv, vv);
                *(float2*)(ob + 2 * cc) = v2;
                *(float2*)(ob + 256 + 2 * cc) = v2;
            }
        }
    }
}

// ---------------------------------------------------------------- launch
extern "C" void kernel_launch(void* const* d_in, const int* in_sizes, int n_in,
                              void* d_out, int out_size) {
    const float* x      = (const float*)d_in[0];
    const float* temp   = (const float*)d_in[1];
    const float* qkv_w  = (const float*)d_in[2];
    const float* dw_w   = (const float*)d_in[3];
    const float* proj_w = (const float*)d_in[4];
    const float* a1 = (const float*)d_in[5];
    const float* a2 = (const float*)d_in[6];
    const float* a3 = (const float*)d_in[7];
    const float* a4 = (const float*)d_in[8];
    float* out = (float*)d_out;

    k_zero<<<96, 256>>>();
    k_qkvpool<<<dim3(6, 512, 4), 256>>>(x, qkv_w);
    k_dw<<<dim3(8, 576, 4), 256>>>(dw_w);
    k_attn<<<dim3(16, 24), 256>>>();
    k_soft<<<96, 256>>>(temp, a1, a2, a3, a4);
    k_av<<<dim3(64, 24), 256>>>();
    k_proj<<<dim3(128, 3, 4), 256>>>(proj_w, out);
}

// round 5
// speedup vs baseline: 1.8599x; 1.0491x over previous
#include <cuda_runtime.h>
#include <cuda_bf16.h>
#include <math.h>

#define Bn 4
#define DIMc 192
#define H3 576
#define HSp 128
#define NPIX 16384
#define HEADS 6
#define CPH 32

typedef unsigned long long u64;

#define FMA2(acc, a, b) \
    asm("fma.rn.f32x2 %0, %1, %2, %0;" : "+l"(acc) : "l"(a), "l"(b))
#define PACKDUP(d, x) \
    asm("mov.b64 %0, {%1, %1};" : "=l"(d) : "f"(x))
#define PACK2(d, lo, hi) \
    asm("mov.b64 %0, {%1, %2};" : "=l"(d) : "f"(lo), "f"(hi))
#define UNPACK2(lo, hi, v) \
    asm("mov.b64 {%0, %1}, %2;" : "=f"(lo), "=f"(hi) : "l"(v))

#define LDM_X4(R, addr) \
    asm volatile("ldmatrix.sync.aligned.m8n8.x4.shared.b16 {%0,%1,%2,%3}, [%4];" \
                 : "=r"((R)[0]), "=r"((R)[1]), "=r"((R)[2]), "=r"((R)[3]) : "r"(addr))
#define LDM_X4T(R, addr) \
    asm volatile("ldmatrix.sync.aligned.m8n8.x4.trans.shared.b16 {%0,%1,%2,%3}, [%4];" \
                 : "=r"((R)[0]), "=r"((R)[1]), "=r"((R)[2]), "=r"((R)[3]) : "r"(addr))
#define MMA_BF16(C, A, b0, b1) \
    asm volatile("mma.sync.aligned.m16n8k16.row.col.f32.bf16.bf16.f32 " \
                 "{%0,%1,%2,%3},{%4,%5,%6,%7},{%8,%9},{%0,%1,%2,%3};" \
                 : "+f"((C)[0]), "+f"((C)[1]), "+f"((C)[2]), "+f"((C)[3]) \
                 : "r"((A)[0]), "r"((A)[1]), "r"((A)[2]), "r"((A)[3]), "r"(b0), "r"(b1))

// ---- scratch ----
__device__ float g_P[Bn * H3 * NPIX];
__device__ float g_D[Bn * H3 * NPIX];
__device__ float g_O[Bn * DIMc * NPIX];
__device__ float g_attn[Bn * HEADS * CPH * CPH];
__device__ float g_A[Bn * HEADS * CPH * CPH];
__device__ float g_normsq[Bn * 2 * DIMc];

// ---------------------------------------------------------------- zero
__global__ void k_zero() {
    int i = blockIdx.x * blockDim.x + threadIdx.x;
    if (i < Bn * HEADS * CPH * CPH) g_attn[i] = 0.f;
    if (i < Bn * 2 * DIMc)          g_normsq[i] = 0.f;
}

// ------------------------------------------- 1x1 qkv conv + 2x2 maxpool
__global__ void __launch_bounds__(256) k_qkvpool(const float* __restrict__ x,
                                                 const float* __restrict__ w) {
    __shared__ __nv_bfloat16 XsH[32][136];
    __shared__ __nv_bfloat16 XsL[32][136];
    __shared__ __nv_bfloat16 WsH[96][40];
    __shared__ __nv_bfloat16 WsL[96][40];
    __shared__ float sPool[96][33];

    int tid = threadIdx.x;
    int b = blockIdx.z;
    int oc0 = blockIdx.x * 96;
    int y = blockIdx.y >> 2, cblk = blockIdx.y & 3;
    int r0 = y * 2, c0 = cblk * 64;
    const float* xb = x + (size_t)b * DIMc * 65536;

    int wid = tid >> 5, l = tid & 31;
    int wm = wid & 1, wn = wid >> 1;
    int m0 = wm * 48, n0 = wn * 32;

    int arow = (l & 7) + ((l >> 3) & 1) * 8;
    int acol8 = (l >> 4) * 8;

    float c[3][4][4];
#pragma unroll
    for (int mf = 0; mf < 3; mf++)
#pragma unroll
        for (int j = 0; j < 4; j++)
#pragma unroll
            for (int q = 0; q < 4; q++) c[mf][j][q] = 0.f;

    for (int k0 = 0; k0 < DIMc; k0 += 32) {
#pragma unroll
        for (int it = 0; it < 8; it++) {
            int idx = tid + it * 256;
            int k = idx >> 6, rem = idx & 63, r = rem >> 5, c2 = rem & 31;
            float2 v = *(const float2*)(xb + (size_t)(k0 + k) * 65536 +
                                        (r0 + r) * 256 + c0 + 2 * c2);
            __nv_bfloat16 h0 = __float2bfloat16(v.x);
            __nv_bfloat16 l0 = __float2bfloat16(v.x - __bfloat162float(h0));
            __nv_bfloat16 h1 = __float2bfloat16(v.y);
            __nv_bfloat16 l1 = __float2bfloat16(v.y - __bfloat162float(h1));
            XsH[k][4 * c2 + r] = h0;     XsL[k][4 * c2 + r] = l0;
            XsH[k][4 * c2 + 2 + r] = h1; XsL[k][4 * c2 + 2 + r] = l1;
        }
#pragma unroll
        for (int it = 0; it < 6; it++) {
            int idx = tid + it * 256;
            int oc = idx >> 4, kk = (idx & 15) * 2;
            float2 v = *(const float2*)(w + (size_t)(oc0 + oc) * DIMc + k0 + kk);
            __nv_bfloat16 h0 = __float2bfloat16(v.x);
            __nv_bfloat16 l0 = __float2bfloat16(v.x - __bfloat162float(h0));
            __nv_bfloat16 h1 = __float2bfloat16(v.y);
            __nv_bfloat16 l1 = __float2bfloat16(v.y - __bfloat162float(h1));
            WsH[oc][kk] = h0;     WsL[oc][kk] = l0;
            WsH[oc][kk + 1] = h1; WsL[oc][kk + 1] = l1;
        }
        __syncthreads();
#pragma unroll
        for (int ks = 0; ks < 2; ks++) {
            unsigned aH[3][4], aL[3][4], bH[2][4], bL[2][4];
#pragma unroll
            for (int mf = 0; mf < 3; mf++) {
                unsigned adrH = (unsigned)__cvta_generic_to_shared(
                    &WsH[m0 + mf * 16 + arow][ks * 16 + acol8]);
                LDM_X4(aH[mf], adrH);
                unsigned adrL = (unsigned)__cvta_generic_to_shared(
                    &WsL[m0 + mf * 16 + arow][ks * 16 + acol8]);
                LDM_X4(aL[mf], adrL);
            }
#pragma unroll
            for (int nb = 0; nb < 2; nb++) {
                unsigned adrH = (unsigned)__cvta_generic_to_shared(
                    &XsH[ks * 16 + arow][n0 + nb * 16 + acol8]);
                LDM_X4T(bH[nb], adrH);
                unsigned adrL = (unsigned)__cvta_generic_to_shared(
                    &XsL[ks * 16 + arow][n0 + nb * 16 + acol8]);
                LDM_X4T(bL[nb], adrL);
            }
#pragma unroll
            for (int mf = 0; mf < 3; mf++)
#pragma unroll
                for (int j = 0; j < 4; j++) {
                    unsigned bh0 = bH[j >> 1][(j & 1) * 2];
                    unsigned bh1 = bH[j >> 1][(j & 1) * 2 + 1];
                    unsigned bl0 = bL[j >> 1][(j & 1) * 2];
                    unsigned bl1 = bL[j >> 1][(j & 1) * 2 + 1];
                    MMA_BF16(c[mf][j], aH[mf], bh0, bh1);
                    MMA_BF16(c[mf][j], aH[mf], bl0, bl1);
                    MMA_BF16(c[mf][j], aL[mf], bh0, bh1);
                }
        }
        __syncthreads();
    }

#pragma unroll
    for (int mf = 0; mf < 3; mf++)
#pragma unroll
        for (int j = 0; j < 4; j++) {
            float v01 = fmaxf(c[mf][j][0], c[mf][j][1]);
            float v23 = fmaxf(c[mf][j][2], c[mf][j][3]);
            float p01 = fmaxf(v01, __shfl_xor_sync(0xffffffffu, v01, 1));
            float p23 = fmaxf(v23, __shfl_xor_sync(0xffffffffu, v23, 1));
            if (!(l & 1)) {
                int hp = wn * 8 + j * 2 + ((l & 2) >> 1);
                int rl = m0 + mf * 16 + (l >> 2);
                sPool[rl][hp] = p01;
                sPool[rl + 8][hp] = p23;
            }
        }
    __syncthreads();
#pragma unroll
    for (int it = 0; it < 12; it++) {
        int t = tid + it * 256;
        int ocl = t >> 5, hx = t & 31;
        g_P[((size_t)b * H3 + oc0 + ocl) * NPIX + y * HSp + cblk * 32 + hx] =
            sPool[ocl][hx];
    }
}

// ------------------------------------------------- depthwise 3x3 (SAME)
__global__ void __launch_bounds__(256) k_dw(const float* __restrict__ dww) {
    __shared__ float sm[18][132];
    int tid = threadIdx.x;
    int ch = blockIdx.y, b = blockIdx.z;
    int rg = blockIdx.x;
    int r0 = rg * 16;
    const float* src = g_P + ((size_t)b * H3 + ch) * NPIX;
    float*       dst = g_D + ((size_t)b * H3 + ch) * NPIX;
    float wgt[9];
#pragma unroll
    for (int i = 0; i < 9; i++) wgt[i] = dww[ch * 9 + i];

#pragma unroll
    for (int it = 0; it < 3; it++) {
        int idx = tid + it * 256;
        if (idx < 18 * 32) {
            int lr = idx >> 5, c4 = (idx & 31) * 4;
            int rr = r0 + lr - 1;
            float4 v = make_float4(0.f, 0.f, 0.f, 0.f);
            if (rr >= 0 && rr < 128)
                v = *(const float4*)(src + rr * 128 + c4);
            sm[lr][1 + c4] = v.x; sm[lr][2 + c4] = v.y;
            sm[lr][3 + c4] = v.z; sm[lr][4 + c4] = v.w;
            if (c4 == 0)  sm[lr][0] = 0.f;
            if (c4 == 124) sm[lr][129] = 0.f;
        }
    }
    __syncthreads();

    float ss = 0.f;
#pragma unroll
    for (int it = 0; it < 8; it++) {
        int p = tid + it * 256;
        int r = p >> 7, cc = p & 127;
        float s = 0.f;
#pragma unroll
        for (int dr = 0; dr < 3; dr++)
#pragma unroll
            for (int dc = 0; dc < 3; dc++)
                s = fmaf(wgt[dr * 3 + dc], sm[r + dr][cc + dc], s);
        dst[r0 * 128 + p] = s;
        ss = fmaf(s, s, ss);
    }
    if (ch < 2 * DIMc) {
#pragma unroll
        for (int o = 16; o > 0; o >>= 1) ss += __shfl_xor_sync(0xffffffffu, ss, o);
        __shared__ float red[8];
        if ((tid & 31) == 0) red[tid >> 5] = ss;
        __syncthreads();
        if (tid < 8) {
            float v = red[tid];
#pragma unroll
            for (int o = 4; o > 0; o >>= 1) v += __shfl_xor_sync(0xffu, v, o);
            if (tid == 0) atomicAdd(&g_normsq[b * 2 * DIMc + ch], v);
        }
    }
}

// ----------------------------------------- attn[b,h,c,d] = sum_n q k
__global__ void __launch_bounds__(256) k_attn() {
    __shared__ float qs[32][65];
    __shared__ float ks[32][65];
    int tid = threadIdx.x;
    int bh = blockIdx.y;
    int b = bh / HEADS, h = bh - b * HEADS;
    int n0 = blockIdx.x * 512;
    const float* qb = g_D + ((size_t)b * H3 + h * CPH) * NPIX;
    const float* kb = g_D + ((size_t)b * H3 + DIMc + h * CPH) * NPIX;
    int dgi = tid & 7, cg = (tid >> 3) & 7, sl = tid >> 6;
    float acc[4][4];
#pragma unroll
    for (int i = 0; i < 4; i++)
#pragma unroll
        for (int j = 0; j < 4; j++) acc[i][j] = 0.f;

    for (int t = 0; t < 8; t++) {
        int n = n0 + t * 64;
#pragma unroll
        for (int it = 0; it < 2; it++) {
            int idx = tid + it * 256;
            int row = idx >> 4, n4 = (idx & 15) * 4;
            float4 q4 = *(const float4*)(qb + (size_t)row * NPIX + n + n4);
            float4 k4 = *(const float4*)(kb + (size_t)row * NPIX + n + n4);
            qs[row][n4 + 0] = q4.x; qs[row][n4 + 1] = q4.y;
            qs[row][n4 + 2] = q4.z; qs[row][n4 + 3] = q4.w;
            ks[row][n4 + 0] = k4.x; ks[row][n4 + 1] = k4.y;
            ks[row][n4 + 2] = k4.z; ks[row][n4 + 3] = k4.w;
        }
        __syncthreads();
#pragma unroll
        for (int nn = sl * 16; nn < sl * 16 + 16; nn++) {
            float qv[4], kv[4];
#pragma unroll
            for (int i = 0; i < 4; i++) qv[i] = qs[cg * 4 + i][nn];
#pragma unroll
            for (int j = 0; j < 4; j++) kv[j] = ks[dgi * 4 + j][nn];
#pragma unroll
            for (int i = 0; i < 4; i++)
#pragma unroll
                for (int j = 0; j < 4; j++)
                    acc[i][j] = fmaf(qv[i], kv[j], acc[i][j]);
        }
        __syncthreads();
    }
#pragma unroll
    for (int i = 0; i < 4; i++)
#pragma unroll
        for (int j = 0; j < 4; j++)
            atomicAdd(&g_attn[((size_t)bh * CPH + cg * 4 + i) * CPH + dgi * 4 + j],
                      acc[i][j]);
}

// --------------- normalize, temperature, 4x top-k masked softmax, combine
__global__ void __launch_bounds__(256) k_soft(const float* __restrict__ temp,
                                              const float* __restrict__ a1,
                                              const float* __restrict__ a2,
                                              const float* __restrict__ a3,
                                              const float* __restrict__ a4) {
    int lane = threadIdx.x & 31;
    int wid = blockIdx.x * 8 + (threadIdx.x >> 5);
    int bh = wid >> 5, c = wid & 31;
    int b = bh / HEADS, h = bh - b * HEADS;
    float v = g_attn[((size_t)bh * CPH + c) * CPH + lane];
    float nq = fmaxf(sqrtf(g_normsq[b * 2 * DIMc + h * CPH + c]), 1e-12f);
    float nk = fmaxf(sqrtf(g_normsq[b * 2 * DIMc + DIMc + h * CPH + lane]), 1e-12f);
    v = v / (nq * nk) * temp[h];
    int rank = 0;
#pragma unroll
    for (int j = 0; j < 32; j++) {
        float vj = __shfl_sync(0xffffffffu, v, j);
        rank += (vj > v || (vj == v && j < lane)) ? 1 : 0;
    }
    float m = v;
#pragma unroll
    for (int o = 16; o > 0; o >>= 1) m = fmaxf(m, __shfl_xor_sync(0xffffffffu, m, o));
    float e = expf(v - m);
    float e16 = rank < 16 ? e : 0.f;
    float e21 = rank < 21 ? e : 0.f;
    float e24 = rank < 24 ? e : 0.f;
    float e25 = rank < 25 ? e : 0.f;
    float s16 = e16, s21 = e21, s24 = e24, s25 = e25;
#pragma unroll
    for (int o = 16; o > 0; o >>= 1) {
        s16 += __shfl_xor_sync(0xffffffffu, s16, o);
        s21 += __shfl_xor_sync(0xffffffffu, s21, o);
        s24 += __shfl_xor_sync(0xffffffffu, s24, o);
        s25 += __shfl_xor_sync(0xffffffffu, s25, o);
    }
    float r = e16 * (a1[0] / s16) + e21 * (a2[0] / s21) +
              e24 * (a3[0] / s24) + e25 * (a4[0] / s25);
    g_A[((size_t)bh * CPH + c) * CPH + lane] = r;
}

// ---------------------------------------------- out = A @ v, exact gelu
__global__ void __launch_bounds__(256) k_av() {
    __shared__ float sA[1024];
    int tid = threadIdx.x;
    int bh = blockIdx.y;
    int b = bh / HEADS, h = bh - b * HEADS;
#pragma unroll
    for (int it = 0; it < 4; it++)
        sA[tid + it * 256] = g_A[(size_t)bh * 1024 + tid + it * 256];
    __syncthreads();
    int n = blockIdx.x * 256 + tid;
    const float* vb = g_D + ((size_t)b * H3 + 2 * DIMc + h * CPH) * NPIX + n;
    u64 vp[16];
#pragma unroll
    for (int d = 0; d < 16; d++) {
        float v0 = vb[(size_t)(2 * d) * NPIX];
        float v1 = vb[(size_t)(2 * d + 1) * NPIX];
        PACK2(vp[d], v0, v1);
    }
    float* ob = g_O + ((size_t)b * DIMc + h * CPH) * NPIX + n;
#pragma unroll
    for (int c2 = 0; c2 < 32; c2++) {
        u64 acc = 0ull;
        const u64* ap = (const u64*)(&sA[c2 * 32]);
#pragma unroll
        for (int d = 0; d < 16; d++)
            FMA2(acc, ap[d], vp[d]);
        float lo, hi;
        UNPACK2(lo, hi, acc);
        float s = lo + hi;
        s = s * normcdff(s);
        ob[(size_t)c2 * NPIX] = s;
    }
}

// -------------------- proj 1x1, tensor-core, upsample-fused epilogue
// C[96 oc][128 halfpix] per block via 3x bf16 split HMMA; each lane's two
// adjacent half-res cols -> one float4 (v0,v0,v1,v1) at full res, x2 rows.
__global__ void __launch_bounds__(256) k_proj(const float* __restrict__ w,
                                              float* __restrict__ out) {
    __shared__ __nv_bfloat16 XsH[32][136];
    __shared__ __nv_bfloat16 XsL[32][136];
    __shared__ __nv_bfloat16 WsH[96][40];
    __shared__ __nv_bfloat16 WsL[96][40];

    int tid = threadIdx.x;
    int b = blockIdx.z;
    int oc0 = blockIdx.y * 96;
    int n0 = blockIdx.x * 128;          // one half-res row (hy = blockIdx.x)
    int hy = blockIdx.x;

    int wid = tid >> 5, l = tid & 31;
    int wm = wid & 1, wn = wid >> 1;
    int m0 = wm * 48, nw0 = wn * 32;

    int arow = (l & 7) + ((l >> 3) & 1) * 8;
    int acol8 = (l >> 4) * 8;

    float c[3][4][4];
#pragma unroll
    for (int mf = 0; mf < 3; mf++)
#pragma unroll
        for (int j = 0; j < 4; j++)
#pragma unroll
            for (int q = 0; q < 4; q++) c[mf][j][q] = 0.f;

    for (int k0 = 0; k0 < DIMc; k0 += 32) {
        // X tile: 32 k x 128 n (fp32 g_O -> hi/lo bf16)
#pragma unroll
        for (int it = 0; it < 8; it++) {
            int idx = tid + it * 256;
            int k = idx >> 6, c2 = idx & 63;
            float2 v = *(const float2*)(g_O + ((size_t)b * DIMc + k0 + k) * NPIX +
                                        n0 + 2 * c2);
            __nv_bfloat16 h0 = __float2bfloat16(v.x);
            __nv_bfloat16 l0 = __float2bfloat16(v.x - __bfloat162float(h0));
            __nv_bfloat16 h1 = __float2bfloat16(v.y);
            __nv_bfloat16 l1 = __float2bfloat16(v.y - __bfloat162float(h1));
            XsH[k][2 * c2] = h0;     XsL[k][2 * c2] = l0;
            XsH[k][2 * c2 + 1] = h1; XsL[k][2 * c2 + 1] = l1;
        }
        // W tile: 96 oc x 32 k
#pragma unroll
        for (int it = 0; it < 6; it++) {
            int idx = tid + it * 256;
            int oc = idx >> 4, kk = (idx & 15) * 2;
            float2 v = *(const float2*)(w + (size_t)(oc0 + oc) * DIMc + k0 + kk);
            __nv_bfloat16 h0 = __float2bfloat16(v.x);
            __nv_bfloat16 l0 = __float2bfloat16(v.x - __bfloat162float(h0));
            __nv_bfloat16 h1 = __float2bfloat16(v.y);
            __nv_bfloat16 l1 = __float2bfloat16(v.y - __bfloat162float(h1));
            WsH[oc][kk] = h0;     WsL[oc][kk] = l0;
            WsH[oc][kk + 1] = h1; WsL[oc][kk + 1] = l1;
        }
        __syncthreads();
#pragma unroll
        for (int ks = 0; ks < 2; ks++) {
            unsigned aH[3][4], aL[3][4], bH[2][4], bL[2][4];
#pragma unroll
            for (int mf = 0; mf < 3; mf++) {
                unsigned adrH = (unsigned)__cvta_generic_to_shared(
                    &WsH[m0 + mf * 16 + arow][ks * 16 + acol8]);
                LDM_X4(aH[mf], adrH);
                unsigned adrL = (unsigned)__cvta_generic_to_shared(
                    &WsL[m0 + mf * 16 + arow][ks * 16 + acol8]);
                LDM_X4(aL[mf], adrL);
            }
#pragma unroll
            for (int nb = 0; nb < 2; nb++) {
                unsigned adrH = (unsigned)__cvta_generic_to_shared(
                    &XsH[ks * 16 + arow][nw0 + nb * 16 + acol8]);
                LDM_X4T(bH[nb], adrH);
                unsigned adrL = (unsigned)__cvta_generic_to_shared(
                    &XsL[ks * 16 + arow][nw0 + nb * 16 + acol8]);
                LDM_X4T(bL[nb], adrL);
            }
#pragma unroll
            for (int mf = 0; mf < 3; mf++)
#pragma unroll
                for (int j = 0; j < 4; j++) {
                    unsigned bh0 = bH[j >> 1][(j & 1) * 2];
                    unsigned bh1 = bH[j >> 1][(j & 1) * 2 + 1];
                    unsigned bl0 = bL[j >> 1][(j & 1) * 2];
                    unsigned bl1 = bL[j >> 1][(j & 1) * 2 + 1];
                    MMA_BF16(c[mf][j], aH[mf], bh0, bh1);
                    MMA_BF16(c[mf][j], aH[mf], bl0, bl1);
                    MMA_BF16(c[mf][j], aL[mf], bh0, bh1);
                }
        }
        __syncthreads();
    }

    // epilogue: nearest 2x upsample fused, float4 stores
    int fr0 = 2 * hy;                      // full-res row pair
#pragma unroll
    for (int mf = 0; mf < 3; mf++)
#pragma unroll
        for (int j = 0; j < 4; j++)
#pragma unroll
            for (int rh = 0; rh < 2; rh++) {
                float v0 = c[mf][j][rh * 2 + 0];
                float v1 = c[mf][j][rh * 2 + 1];
                int oc = oc0 + m0 + mf * 16 + (l >> 2) + 8 * rh;
                int hc = nw0 + (j >> 1) * 16 + (j & 1) * 8 + 2 * (l & 3);
                float4 v4 = make_float4(v0, v0, v1, v1);
                float* ob = out + ((size_t)b * DIMc + oc) * 65536 +
                            fr0 * 256 + 2 * hc;
                *(float4*)ob = v4;
                *(float4*)(ob + 256) = v4;
            }
}

// ---------------------------------------------------------------- launch
extern "C" void kernel_launch(void* const* d_in, const int* in_sizes, int n_in,
                              void* d_out, int out_size) {
    const float* x      = (const float*)d_in[0];
    const float* temp   = (const float*)d_in[1];
    const float* qkv_w  = (const float*)d_in[2];
    const float* dw_w   = (const float*)d_in[3];
    const float* proj_w = (const float*)d_in[4];
    const float* a1 = (const float*)d_in[5];
    const float* a2 = (const float*)d_in[6];
    const float* a3 = (const float*)d_in[7];
    const float* a4 = (const float*)d_in[8];
    float* out = (float*)d_out;

    k_zero<<<96, 256>>>();
    k_qkvpool<<<dim3(6, 512, 4), 256>>>(x, qkv_w);
    k_dw<<<dim3(8, 576, 4), 256>>>(dw_w);
    k_attn<<<dim3(32, 24), 256>>>();
    k_soft<<<96, 256>>>(temp, a1, a2, a3, a4);
    k_av<<<dim3(64, 24), 256>>>();
    k_proj<<<dim3(128, 2, 4), 256>>>(proj_w, out);
}

// round 6
// speedup vs baseline: 2.0538x; 1.1043x over previous
#include <cuda_runtime.h>
#include <cuda_bf16.h>
#include <math.h>

#define Bn 4
#define DIMc 192
#define H3 576
#define HSp 128
#define NPIX 16384
#define HEADS 6
#define CPH 32

typedef unsigned long long u64;

#define FMA2(acc, a, b) \
    asm("fma.rn.f32x2 %0, %1, %2, %0;" : "+l"(acc) : "l"(a), "l"(b))
#define PACK2(d, lo, hi) \
    asm("mov.b64 %0, {%1, %2};" : "=l"(d) : "f"(lo), "f"(hi))
#define UNPACK2(lo, hi, v) \
    asm("mov.b64 {%0, %1}, %2;" : "=f"(lo), "=f"(hi) : "l"(v))

#define LDM_X4(R, addr) \
    asm volatile("ldmatrix.sync.aligned.m8n8.x4.shared.b16 {%0,%1,%2,%3}, [%4];" \
                 : "=r"((R)[0]), "=r"((R)[1]), "=r"((R)[2]), "=r"((R)[3]) : "r"(addr))
#define LDM_X4T(R, addr) \
    asm volatile("ldmatrix.sync.aligned.m8n8.x4.trans.shared.b16 {%0,%1,%2,%3}, [%4];" \
                 : "=r"((R)[0]), "=r"((R)[1]), "=r"((R)[2]), "=r"((R)[3]) : "r"(addr))
#define MMA_BF16(C, A, b0, b1) \
    asm volatile("mma.sync.aligned.m16n8k16.row.col.f32.bf16.bf16.f32 " \
                 "{%0,%1,%2,%3},{%4,%5,%6,%7},{%8,%9},{%0,%1,%2,%3};" \
                 : "+f"((C)[0]), "+f"((C)[1]), "+f"((C)[2]), "+f"((C)[3]) \
                 : "r"((A)[0]), "r"((A)[1]), "r"((A)[2]), "r"((A)[3]), "r"(b0), "r"(b1))

// ---- scratch ----
__device__ float g_P[Bn * H3 * NPIX];
__device__ float g_D[Bn * H3 * NPIX];
__device__ float g_attn[Bn * HEADS * CPH * CPH];
__device__ float g_A[Bn * HEADS * CPH * CPH];
__device__ float g_normsq[Bn * 2 * DIMc];
// pre-split bf16 hi/lo buffers
__device__ __nv_bfloat16 g_XH[Bn * DIMc * 65536];   // quad layout
__device__ __nv_bfloat16 g_XL[Bn * DIMc * 65536];
__device__ __nv_bfloat16 g_WH[H3 * DIMc];
__device__ __nv_bfloat16 g_WL[H3 * DIMc];
__device__ __nv_bfloat16 g_PWH[DIMc * DIMc];
__device__ __nv_bfloat16 g_PWL[DIMc * DIMc];
__device__ __nv_bfloat16 g_OH[Bn * DIMc * NPIX];    // gelu(av) hi/lo
__device__ __nv_bfloat16 g_OL[Bn * DIMc * NPIX];

// ---------------------------------------------------------------- zero
__global__ void k_zero() {
    int i = blockIdx.x * blockDim.x + threadIdx.x;
    if (i < Bn * HEADS * CPH * CPH) g_attn[i] = 0.f;
    if (i < Bn * 2 * DIMc)          g_normsq[i] = 0.f;
}

// ------------------- split x into hi/lo bf16, pool-quad layout
// out[(bk)*65536 + hp*4 + q], q = 2*dc + dr for the 2x2 pool quad of hp
__global__ void __launch_bounds__(256) k_splitX(const float* __restrict__ x) {
    int bk = blockIdx.x;
    const float* src = x + (size_t)bk * 65536;
    __nv_bfloat16* dH = g_XH + (size_t)bk * 65536;
    __nv_bfloat16* dL = g_XL + (size_t)bk * 65536;
#pragma unroll 4
    for (int i = 0; i < 64; i++) {
        int hp = threadIdx.x + i * 256;
        int hy = hp >> 7, hx = hp & 127;
        float2 a = *(const float2*)(src + (2 * hy) * 256 + 2 * hx);
        float2 bv = *(const float2*)(src + (2 * hy + 1) * 256 + 2 * hx);
        float v0 = a.x, v1 = bv.x, v2 = a.y, v3 = bv.y;
        __nv_bfloat16 h0 = __float2bfloat16(v0), h1 = __float2bfloat16(v1);
        __nv_bfloat16 h2 = __float2bfloat16(v2), h3 = __float2bfloat16(v3);
        __nv_bfloat162 H01, H23, L01, L23;
        H01.x = h0; H01.y = h1; H23.x = h2; H23.y = h3;
        L01.x = __float2bfloat16(v0 - __bfloat162float(h0));
        L01.y = __float2bfloat16(v1 - __bfloat162float(h1));
        L23.x = __float2bfloat16(v2 - __bfloat162float(h2));
        L23.y = __float2bfloat16(v3 - __bfloat162float(h3));
        *(__nv_bfloat162*)(dH + hp * 4) = H01;
        *(__nv_bfloat162*)(dH + hp * 4 + 2) = H23;
        *(__nv_bfloat162*)(dL + hp * 4) = L01;
        *(__nv_bfloat162*)(dL + hp * 4 + 2) = L23;
    }
}

// ------------------- split qkv_w and proj_w
__global__ void k_splitW(const float* __restrict__ qw,
                         const float* __restrict__ pw) {
    int i = blockIdx.x * 256 + threadIdx.x;
    if (i < H3 * DIMc) {
        float v = qw[i];
        __nv_bfloat16 h = __float2bfloat16(v);
        g_WH[i] = h;
        g_WL[i] = __float2bfloat16(v - __bfloat162float(h));
    }
    if (i < DIMc * DIMc) {
        float v = pw[i];
        __nv_bfloat16 h = __float2bfloat16(v);
        g_PWH[i] = h;
        g_PWL[i] = __float2bfloat16(v - __bfloat162float(h));
    }
}

// ------------------------------------------- 1x1 qkv conv + 2x2 maxpool
__global__ void __launch_bounds__(256) k_qkvpool() {
    __shared__ __nv_bfloat16 XsH[32][136];
    __shared__ __nv_bfloat16 XsL[32][136];
    __shared__ __nv_bfloat16 WsH[96][40];
    __shared__ __nv_bfloat16 WsL[96][40];
    __shared__ float sPool[96][33];

    int tid = threadIdx.x;
    int b = blockIdx.z;
    int oc0 = blockIdx.x * 96;
    int y = blockIdx.y >> 2, cblk = blockIdx.y & 3;
    int px0 = y * 512 + cblk * 128;          // quad-layout offset within channel

    int wid = tid >> 5, l = tid & 31;
    int wm = wid & 1, wn = wid >> 1;
    int m0 = wm * 48, n0 = wn * 32;

    int arow = (l & 7) + ((l >> 3) & 1) * 8;
    int acol8 = (l >> 4) * 8;

    float c[3][4][4];
#pragma unroll
    for (int mf = 0; mf < 3; mf++)
#pragma unroll
        for (int j = 0; j < 4; j++)
#pragma unroll
            for (int q = 0; q < 4; q++) c[mf][j][q] = 0.f;

    for (int k0 = 0; k0 < DIMc; k0 += 32) {
        // X tile: straight uint4 copies (presplit, quad-ordered)
#pragma unroll
        for (int it = 0; it < 2; it++) {
            int idx = tid + it * 256;        // 512
            int k = idx >> 4, c8 = (idx & 15) * 8;
            size_t off = (((size_t)b * DIMc + k0 + k) << 16) + px0 + c8;
            *(uint4*)(&XsH[k][c8]) = *(const uint4*)(g_XH + off);
            *(uint4*)(&XsL[k][c8]) = *(const uint4*)(g_XL + off);
        }
        // W tile: 96 oc x 32 k
#pragma unroll
        for (int it = 0; it < 2; it++) {
            int idx = tid + it * 256;
            if (idx < 384) {
                int oc = idx >> 2, k8 = (idx & 3) * 8;
                size_t off = (size_t)(oc0 + oc) * DIMc + k0 + k8;
                *(uint4*)(&WsH[oc][k8]) = *(const uint4*)(g_WH + off);
                *(uint4*)(&WsL[oc][k8]) = *(const uint4*)(g_WL + off);
            }
        }
        __syncthreads();
#pragma unroll
        for (int ks = 0; ks < 2; ks++) {
            unsigned aH[3][4], aL[3][4], bH[2][4], bL[2][4];
#pragma unroll
            for (int mf = 0; mf < 3; mf++) {
                unsigned adrH = (unsigned)__cvta_generic_to_shared(
                    &WsH[m0 + mf * 16 + arow][ks * 16 + acol8]);
                LDM_X4(aH[mf], adrH);
                unsigned adrL = (unsigned)__cvta_generic_to_shared(
                    &WsL[m0 + mf * 16 + arow][ks * 16 + acol8]);
                LDM_X4(aL[mf], adrL);
            }
#pragma unroll
            for (int nb = 0; nb < 2; nb++) {
                unsigned adrH = (unsigned)__cvta_generic_to_shared(
                    &XsH[ks * 16 + arow][n0 + nb * 16 + acol8]);
                LDM_X4T(bH[nb], adrH);
                unsigned adrL = (unsigned)__cvta_generic_to_shared(
                    &XsL[ks * 16 + arow][n0 + nb * 16 + acol8]);
                LDM_X4T(bL[nb], adrL);
            }
#pragma unroll
            for (int mf = 0; mf < 3; mf++)
#pragma unroll
                for (int j = 0; j < 4; j++) {
                    unsigned bh0 = bH[j >> 1][(j & 1) * 2];
                    unsigned bh1 = bH[j >> 1][(j & 1) * 2 + 1];
                    unsigned bl0 = bL[j >> 1][(j & 1) * 2];
                    unsigned bl1 = bL[j >> 1][(j & 1) * 2 + 1];
                    MMA_BF16(c[mf][j], aH[mf], bh0, bh1);
                    MMA_BF16(c[mf][j], aH[mf], bl0, bl1);
                    MMA_BF16(c[mf][j], aL[mf], bh0, bh1);
                }
        }
        __syncthreads();
    }

#pragma unroll
    for (int mf = 0; mf < 3; mf++)
#pragma unroll
        for (int j = 0; j < 4; j++) {
            float v01 = fmaxf(c[mf][j][0], c[mf][j][1]);
            float v23 = fmaxf(c[mf][j][2], c[mf][j][3]);
            float p01 = fmaxf(v01, __shfl_xor_sync(0xffffffffu, v01, 1));
            float p23 = fmaxf(v23, __shfl_xor_sync(0xffffffffu, v23, 1));
            if (!(l & 1)) {
                int hp = wn * 8 + j * 2 + ((l & 2) >> 1);
                int rl = m0 + mf * 16 + (l >> 2);
                sPool[rl][hp] = p01;
                sPool[rl + 8][hp] = p23;
            }
        }
    __syncthreads();
#pragma unroll
    for (int it = 0; it < 12; it++) {
        int t = tid + it * 256;
        int ocl = t >> 5, hx = t & 31;
        g_P[((size_t)b * H3 + oc0 + ocl) * NPIX + y * HSp + cblk * 32 + hx] =
            sPool[ocl][hx];
    }
}

// ------------------------------------------------- depthwise 3x3 (SAME)
__global__ void __launch_bounds__(256) k_dw(const float* __restrict__ dww) {
    __shared__ float sm[18][132];
    int tid = threadIdx.x;
    int ch = blockIdx.y, b = blockIdx.z;
    int rg = blockIdx.x;
    int r0 = rg * 16;
    const float* src = g_P + ((size_t)b * H3 + ch) * NPIX;
    float*       dst = g_D + ((size_t)b * H3 + ch) * NPIX;
    float wgt[9];
#pragma unroll
    for (int i = 0; i < 9; i++) wgt[i] = dww[ch * 9 + i];

#pragma unroll
    for (int it = 0; it < 3; it++) {
        int idx = tid + it * 256;
        if (idx < 18 * 32) {
            int lr = idx >> 5, c4 = (idx & 31) * 4;
            int rr = r0 + lr - 1;
            float4 v = make_float4(0.f, 0.f, 0.f, 0.f);
            if (rr >= 0 && rr < 128)
                v = *(const float4*)(src + rr * 128 + c4);
            sm[lr][1 + c4] = v.x; sm[lr][2 + c4] = v.y;
            sm[lr][3 + c4] = v.z; sm[lr][4 + c4] = v.w;
            if (c4 == 0)  sm[lr][0] = 0.f;
            if (c4 == 124) sm[lr][129] = 0.f;
        }
    }
    __syncthreads();

    float ss = 0.f;
#pragma unroll
    for (int it = 0; it < 8; it++) {
        int p = tid + it * 256;
        int r = p >> 7, cc = p & 127;
        float s = 0.f;
#pragma unroll
        for (int dr = 0; dr < 3; dr++)
#pragma unroll
            for (int dc = 0; dc < 3; dc++)
                s = fmaf(wgt[dr * 3 + dc], sm[r + dr][cc + dc], s);
        dst[r0 * 128 + p] = s;
        ss = fmaf(s, s, ss);
    }
    if (ch < 2 * DIMc) {
#pragma unroll
        for (int o = 16; o > 0; o >>= 1) ss += __shfl_xor_sync(0xffffffffu, ss, o);
        __shared__ float red[8];
        if ((tid & 31) == 0) red[tid >> 5] = ss;
        __syncthreads();
        if (tid < 8) {
            float v = red[tid];
#pragma unroll
            for (int o = 4; o > 0; o >>= 1) v += __shfl_xor_sync(0xffu, v, o);
            if (tid == 0) atomicAdd(&g_normsq[b * 2 * DIMc + ch], v);
        }
    }
}

// ----------------------------------------- attn[b,h,c,d] = sum_n q k
__global__ void __launch_bounds__(256) k_attn() {
    __shared__ float qs[32][65];
    __shared__ float ks[32][65];
    int tid = threadIdx.x;
    int bh = blockIdx.y;
    int b = bh / HEADS, h = bh - b * HEADS;
    int n0 = blockIdx.x * 1024;
    const float* qb = g_D + ((size_t)b * H3 + h * CPH) * NPIX;
    const float* kb = g_D + ((size_t)b * H3 + DIMc + h * CPH) * NPIX;
    int dgi = tid & 7, cg = (tid >> 3) & 7, sl = tid >> 6;
    float acc[4][4];
#pragma unroll
    for (int i = 0; i < 4; i++)
#pragma unroll
        for (int j = 0; j < 4; j++) acc[i][j] = 0.f;

    for (int t = 0; t < 16; t++) {
        int n = n0 + t * 64;
#pragma unroll
        for (int it = 0; it < 2; it++) {
            int idx = tid + it * 256;
            int row = idx >> 4, n4 = (idx & 15) * 4;
            float4 q4 = *(const float4*)(qb + (size_t)row * NPIX + n + n4);
            float4 k4 = *(const float4*)(kb + (size_t)row * NPIX + n + n4);
            qs[row][n4 + 0] = q4.x; qs[row][n4 + 1] = q4.y;
            qs[row][n4 + 2] = q4.z; qs[row][n4 + 3] = q4.w;
            ks[row][n4 + 0] = k4.x; ks[row][n4 + 1] = k4.y;
            ks[row][n4 + 2] = k4.z; ks[row][n4 + 3] = k4.w;
        }
        __syncthreads();
#pragma unroll
        for (int nn = sl * 16; nn < sl * 16 + 16; nn++) {
            float qv[4], kv[4];
#pragma unroll
            for (int i = 0; i < 4; i++) qv[i] = qs[cg * 4 + i][nn];
#pragma unroll
            for (int j = 0; j < 4; j++) kv[j] = ks[dgi * 4 + j][nn];
#pragma unroll
            for (int i = 0; i < 4; i++)
#pragma unroll
                for (int j = 0; j < 4; j++)
                    acc[i][j] = fmaf(qv[i], kv[j], acc[i][j]);
        }
        __syncthreads();
    }
#pragma unroll
    for (int i = 0; i < 4; i++)
#pragma unroll
        for (int j = 0; j < 4; j++)
            atomicAdd(&g_attn[((size_t)bh * CPH + cg * 4 + i) * CPH + dgi * 4 + j],
                      acc[i][j]);
}

// --------------- normalize, temperature, 4x top-k masked softmax, combine
__global__ void __launch_bounds__(256) k_soft(const float* __restrict__ temp,
                                              const float* __restrict__ a1,
                                              const float* __restrict__ a2,
                                              const float* __restrict__ a3,
                                              const float* __restrict__ a4) {
    int lane = threadIdx.x & 31;
    int wid = blockIdx.x * 8 + (threadIdx.x >> 5);
    int bh = wid >> 5, c = wid & 31;
    int b = bh / HEADS, h = bh - b * HEADS;
    float v = g_attn[((size_t)bh * CPH + c) * CPH + lane];
    float nq = fmaxf(sqrtf(g_normsq[b * 2 * DIMc + h * CPH + c]), 1e-12f);
    float nk = fmaxf(sqrtf(g_normsq[b * 2 * DIMc + DIMc + h * CPH + lane]), 1e-12f);
    v = v / (nq * nk) * temp[h];
    int rank = 0;
#pragma unroll
    for (int j = 0; j < 32; j++) {
        float vj = __shfl_sync(0xffffffffu, v, j);
        rank += (vj > v || (vj == v && j < lane)) ? 1 : 0;
    }
    float m = v;
#pragma unroll
    for (int o = 16; o > 0; o >>= 1) m = fmaxf(m, __shfl_xor_sync(0xffffffffu, m, o));
    float e = expf(v - m);
    float e16 = rank < 16 ? e : 0.f;
    float e21 = rank < 21 ? e : 0.f;
    float e24 = rank < 24 ? e : 0.f;
    float e25 = rank < 25 ? e : 0.f;
    float s16 = e16, s21 = e21, s24 = e24, s25 = e25;
#pragma unroll
    for (int o = 16; o > 0; o >>= 1) {
        s16 += __shfl_xor_sync(0xffffffffu, s16, o);
        s21 += __shfl_xor_sync(0xffffffffu, s21, o);
        s24 += __shfl_xor_sync(0xffffffffu, s24, o);
        s25 += __shfl_xor_sync(0xffffffffu, s25, o);
    }
    float r = e16 * (a1[0] / s16) + e21 * (a2[0] / s21) +
              e24 * (a3[0] / s24) + e25 * (a4[0] / s25);
    g_A[((size_t)bh * CPH + c) * CPH + lane] = r;
}

// ------------------- out = gelu(A @ v), written as bf16 hi/lo for proj
__global__ void __launch_bounds__(256) k_av() {
    __shared__ float sA[1024];
    int tid = threadIdx.x;
    int bh = blockIdx.y;
    int b = bh / HEADS, h = bh - b * HEADS;
#pragma unroll
    for (int it = 0; it < 4; it++)
        sA[tid + it * 256] = g_A[(size_t)bh * 1024 + tid + it * 256];
    __syncthreads();
    int n = blockIdx.x * 256 + tid;
    const float* vb = g_D + ((size_t)b * H3 + 2 * DIMc + h * CPH) * NPIX + n;
    u64 vp[16];
#pragma unroll
    for (int d = 0; d < 16; d++) {
        float v0 = vb[(size_t)(2 * d) * NPIX];
        float v1 = vb[(size_t)(2 * d + 1) * NPIX];
        PACK2(vp[d], v0, v1);
    }
    size_t ob = ((size_t)b * DIMc + h * CPH) * NPIX + n;
#pragma unroll
    for (int c2 = 0; c2 < 32; c2++) {
        u64 acc = 0ull;
        const u64* ap = (const u64*)(&sA[c2 * 32]);
#pragma unroll
        for (int d = 0; d < 16; d++)
            FMA2(acc, ap[d], vp[d]);
        float lo, hi;
        UNPACK2(lo, hi, acc);
        float s = lo + hi;
        s = s * normcdff(s);
        __nv_bfloat16 hh = __float2bfloat16(s);
        g_OH[ob + (size_t)c2 * NPIX] = hh;
        g_OL[ob + (size_t)c2 * NPIX] = __float2bfloat16(s - __bfloat162float(hh));
    }
}

// -------------------- proj 1x1, tensor-core, upsample-fused epilogue
__global__ void __launch_bounds__(256) k_proj(float* __restrict__ out) {
    __shared__ __nv_bfloat16 XsH[32][136];
    __shared__ __nv_bfloat16 XsL[32][136];
    __shared__ __nv_bfloat16 WsH[96][40];
    __shared__ __nv_bfloat16 WsL[96][40];

    int tid = threadIdx.x;
    int b = blockIdx.z;
    int oc0 = blockIdx.y * 96;
    int n0 = blockIdx.x * 128;
    int hy = blockIdx.x;

    int wid = tid >> 5, l = tid & 31;
    int wm = wid & 1, wn = wid >> 1;
    int m0 = wm * 48, nw0 = wn * 32;

    int arow = (l & 7) + ((l >> 3) & 1) * 8;
    int acol8 = (l >> 4) * 8;

    float c[3][4][4];
#pragma unroll
    for (int mf = 0; mf < 3; mf++)
#pragma unroll
        for (int j = 0; j < 4; j++)
#pragma unroll
            for (int q = 0; q < 4; q++) c[mf][j][q] = 0.f;

    for (int k0 = 0; k0 < DIMc; k0 += 32) {
#pragma unroll
        for (int it = 0; it < 2; it++) {
            int idx = tid + it * 256;
            int k = idx >> 4, c8 = (idx & 15) * 8;
            size_t off = ((size_t)b * DIMc + k0 + k) * NPIX + n0 + c8;
            *(uint4*)(&XsH[k][c8]) = *(const uint4*)(g_OH + off);
            *(uint4*)(&XsL[k][c8]) = *(const uint4*)(g_OL + off);
        }
#pragma unroll
        for (int it = 0; it < 2; it++) {
            int idx = tid + it * 256;
            if (idx < 384) {
                int oc = idx >> 2, k8 = (idx & 3) * 8;
                size_t off = (size_t)(oc0 + oc) * DIMc + k0 + k8;
                *(uint4*)(&WsH[oc][k8]) = *(const uint4*)(g_PWH + off);
                *(uint4*)(&WsL[oc][k8]) = *(const uint4*)(g_PWL + off);
            }
        }
        __syncthreads();
#pragma unroll
        for (int ks = 0; ks < 2; ks++) {
            unsigned aH[3][4], aL[3][4], bH[2][4], bL[2][4];
#pragma unroll
            for (int mf = 0; mf < 3; mf++) {
                unsigned adrH = (unsigned)__cvta_generic_to_shared(
                    &WsH[m0 + mf * 16 + arow][ks * 16 + acol8]);
                LDM_X4(aH[mf], adrH);
                unsigned adrL = (unsigned)__cvta_generic_to_shared(
                    &WsL[m0 + mf * 16 + arow][ks * 16 + acol8]);
                LDM_X4(aL[mf], adrL);
            }
#pragma unroll
            for (int nb = 0; nb < 2; nb++) {
                unsigned adrH = (unsigned)__cvta_generic_to_shared(
                    &XsH[ks * 16 + arow][nw0 + nb * 16 + acol8]);
                LDM_X4T(bH[nb], adrH);
                unsigned adrL = (unsigned)__cvta_generic_to_shared(
                    &XsL[ks * 16 + arow][nw0 + nb * 16 + acol8]);
                LDM_X4T(bL[nb], adrL);
            }
#pragma unroll
            for (int mf = 0; mf < 3; mf++)
#pragma unroll
                for (int j = 0; j < 4; j++) {
                    unsigned bh0 = bH[j >> 1][(j & 1) * 2];
                    unsigned bh1 = bH[j >> 1][(j & 1) * 2 + 1];
                    unsigned bl0 = bL[j >> 1][(j & 1) * 2];
                    unsigned bl1 = bL[j >> 1][(j & 1) * 2 + 1];
                    MMA_BF16(c[mf][j], aH[mf], bh0, bh1);
                    MMA_BF16(c[mf][j], aH[mf], bl0, bl1);
                    MMA_BF16(c[mf][j], aL[mf], bh0, bh1);
                }
        }
        __syncthreads();
    }

    int fr0 = 2 * hy;
#pragma unroll
    for (int mf = 0; mf < 3; mf++)
#pragma unroll
        for (int j = 0; j < 4; j++)
#pragma unroll
            for (int rh = 0; rh < 2; rh++) {
                float v0 = c[mf][j][rh * 2 + 0];
                float v1 = c[mf][j][rh * 2 + 1];
                int oc = oc0 + m0 + mf * 16 + (l >> 2) + 8 * rh;
                int hc = nw0 + (j >> 1) * 16 + (j & 1) * 8 + 2 * (l & 3);
                float4 v4 = make_float4(v0, v0, v1, v1);
                float* ob = out + ((size_t)b * DIMc + oc) * 65536 +
                            fr0 * 256 + 2 * hc;
                *(float4*)ob = v4;
                *(float4*)(ob + 256) = v4;
            }
}

// ---------------------------------------------------------------- launch
extern "C" void kernel_launch(void* const* d_in, const int* in_sizes, int n_in,
                              void* d_out, int out_size) {
    const float* x      = (const float*)d_in[0];
    const float* temp   = (const float*)d_in[1];
    const float* qkv_w  = (const float*)d_in[2];
    const float* dw_w   = (const float*)d_in[3];
    const float* proj_w = (const float*)d_in[4];
    const float* a1 = (const float*)d_in[5];
    const float* a2 = (const float*)d_in[6];
    const float* a3 = (const float*)d_in[7];
    const float* a4 = (const float*)d_in[8];
    float* out = (float*)d_out;

    k_zero<<<96, 256>>>();
    k_splitX<<<Bn * DIMc, 256>>>(x);
    k_splitW<<<432, 256>>>(qkv_w, proj_w);
    k_qkvpool<<<dim3(6, 512, 4), 256>>>();
    k_dw<<<dim3(8, 576, 4), 256>>>(dw_w);
    k_attn<<<dim3(16, 24), 256>>>();
    k_soft<<<96, 256>>>(temp, a1, a2, a3, a4);
    k_av<<<dim3(64, 24), 256>>>();
    k_proj<<<dim3(128, 2, 4), 256>>>(out);
}

// round 8
// speedup vs baseline: 2.2583x; 1.0996x over previous
#include <cuda_runtime.h>
#include <cuda_bf16.h>
#include <math.h>

#define Bn 4
#define DIMc 192
#define H3 576
#define HSp 128
#define NPIX 16384
#define HEADS 6
#define CPH 32

typedef unsigned long long u64;

#define FMA2(acc, a, b) \
    asm("fma.rn.f32x2 %0, %1, %2, %0;" : "+l"(acc) : "l"(a), "l"(b))
#define PACK2(d, lo, hi) \
    asm("mov.b64 %0, {%1, %2};" : "=l"(d) : "f"(lo), "f"(hi))
#define UNPACK2(lo, hi, v) \
    asm("mov.b64 {%0, %1}, %2;" : "=f"(lo), "=f"(hi) : "l"(v))

#define LDM_X4(R, addr) \
    asm volatile("ldmatrix.sync.aligned.m8n8.x4.shared.b16 {%0,%1,%2,%3}, [%4];" \
                 : "=r"((R)[0]), "=r"((R)[1]), "=r"((R)[2]), "=r"((R)[3]) : "r"(addr))
#define LDM_X4T(R, addr) \
    asm volatile("ldmatrix.sync.aligned.m8n8.x4.trans.shared.b16 {%0,%1,%2,%3}, [%4];" \
                 : "=r"((R)[0]), "=r"((R)[1]), "=r"((R)[2]), "=r"((R)[3]) : "r"(addr))
#define MMA_BF16(C, A, b0, b1) \
    asm volatile("mma.sync.aligned.m16n8k16.row.col.f32.bf16.bf16.f32 " \
                 "{%0,%1,%2,%3},{%4,%5,%6,%7},{%8,%9},{%0,%1,%2,%3};" \
                 : "+f"((C)[0]), "+f"((C)[1]), "+f"((C)[2]), "+f"((C)[3]) \
                 : "r"((A)[0]), "r"((A)[1]), "r"((A)[2]), "r"((A)[3]), "r"(b0), "r"(b1))

#define CPA(dst, src) \
    asm volatile("cp.async.cg.shared.global [%0], [%1], 16;" :: "r"(dst), "l"(src))
#define CPC() asm volatile("cp.async.commit_group;")
#define CPW1() asm volatile("cp.async.wait_group 1;")
#define CPW0() asm volatile("cp.async.wait_group 0;")

// ---- scratch ----
__device__ float g_P[Bn * H3 * NPIX];
__device__ float g_D[Bn * H3 * NPIX];
__device__ float g_attn[Bn * HEADS * CPH * CPH];
__device__ float g_A[Bn * HEADS * CPH * CPH];
__device__ float g_normsq[Bn * 2 * DIMc];
__device__ __nv_bfloat16 g_XH[Bn * DIMc * 65536];
__device__ __nv_bfloat16 g_XL[Bn * DIMc * 65536];
__device__ __nv_bfloat16 g_WH[H3 * DIMc];
__device__ __nv_bfloat16 g_WL[H3 * DIMc];
__device__ __nv_bfloat16 g_PWH[DIMc * DIMc];
__device__ __nv_bfloat16 g_PWL[DIMc * DIMc];
__device__ __nv_bfloat16 g_OH[Bn * DIMc * NPIX];
__device__ __nv_bfloat16 g_OL[Bn * DIMc * NPIX];

// dynamic smem layout (elements)
#define XSTRIDE 136
#define XELEMS (32 * XSTRIDE)
#define WSTRIDE 40
#define WELEMS (96 * WSTRIDE)
#define OFF_XH 0
#define OFF_XL (2 * XELEMS)
#define OFF_WH (4 * XELEMS)
#define OFF_WL (4 * XELEMS + 2 * WELEMS)
#define SM_GEMM_ELEMS (4 * XELEMS + 4 * WELEMS)          // bf16 elements
#define SMEM_QKV_BYTES (SM_GEMM_ELEMS * 2 + 96 * 33 * 4) // + sPool bytes
#define SMEM_PROJ_BYTES (SM_GEMM_ELEMS * 2)

// ---------------------------------------------------------------- zero
__global__ void k_zero() {
    int i = blockIdx.x * blockDim.x + threadIdx.x;
    if (i < Bn * HEADS * CPH * CPH) g_attn[i] = 0.f;
    if (i < Bn * 2 * DIMc)          g_normsq[i] = 0.f;
}

// ------------------- split x into hi/lo bf16, pool-quad layout
__global__ void __launch_bounds__(256) k_splitX(const float* __restrict__ x) {
    int bk = blockIdx.x;
    const float* src = x + (size_t)bk * 65536;
    __nv_bfloat16* dH = g_XH + (size_t)bk * 65536;
    __nv_bfloat16* dL = g_XL + (size_t)bk * 65536;
#pragma unroll 4
    for (int i = 0; i < 64; i++) {
        int hp = threadIdx.x + i * 256;
        int hy = hp >> 7, hx = hp & 127;
        float2 a = *(const float2*)(src + (2 * hy) * 256 + 2 * hx);
        float2 bv = *(const float2*)(src + (2 * hy + 1) * 256 + 2 * hx);
        float v0 = a.x, v1 = bv.x, v2 = a.y, v3 = bv.y;
        __nv_bfloat16 h0 = __float2bfloat16(v0), h1 = __float2bfloat16(v1);
        __nv_bfloat16 h2 = __float2bfloat16(v2), h3 = __float2bfloat16(v3);
        __nv_bfloat162 H01, H23, L01, L23;
        H01.x = h0; H01.y = h1; H23.x = h2; H23.y = h3;
        L01.x = __float2bfloat16(v0 - __bfloat162float(h0));
        L01.y = __float2bfloat16(v1 - __bfloat162float(h1));
        L23.x = __float2bfloat16(v2 - __bfloat162float(h2));
        L23.y = __float2bfloat16(v3 - __bfloat162float(h3));
        *(__nv_bfloat162*)(dH + hp * 4) = H01;
        *(__nv_bfloat162*)(dH + hp * 4 + 2) = H23;
        *(__nv_bfloat162*)(dL + hp * 4) = L01;
        *(__nv_bfloat162*)(dL + hp * 4 + 2) = L23;
    }
}

// ------------------- split qkv_w and proj_w
__global__ void k_splitW(const float* __restrict__ qw,
                         const float* __restrict__ pw) {
    int i = blockIdx.x * 256 + threadIdx.x;
    if (i < H3 * DIMc) {
        float v = qw[i];
        __nv_bfloat16 h = __float2bfloat16(v);
        g_WH[i] = h;
        g_WL[i] = __float2bfloat16(v - __bfloat162float(h));
    }
    if (i < DIMc * DIMc) {
        float v = pw[i];
        __nv_bfloat16 h = __float2bfloat16(v);
        g_PWH[i] = h;
        g_PWL[i] = __float2bfloat16(v - __bfloat162float(h));
    }
}

// ------------------------------------------- 1x1 qkv conv + 2x2 maxpool
// double-buffered cp.async pipeline, 96oc x 128px, K=192
__global__ void __launch_bounds__(256) k_qkvpool() {
    extern __shared__ __nv_bfloat16 sm[];
    float* sPool = (float*)(sm + SM_GEMM_ELEMS);   // FIX: element offset

    int tid = threadIdx.x;
    int b = blockIdx.z;
    int oc0 = blockIdx.x * 96;
    int y = blockIdx.y >> 2, cblk = blockIdx.y & 3;
    int px0 = y * 512 + cblk * 128;

    int wid = tid >> 5, l = tid & 31;
    int wm = wid & 1, wn = wid >> 1;
    int m0 = wm * 48, n0 = wn * 32;
    int arow = (l & 7) + ((l >> 3) & 1) * 8;
    int acol8 = (l >> 4) * 8;

    int xk = tid >> 4, xc8 = (tid & 15) * 8;

    auto load_stage = [&](int s, int k0) {
        size_t xbase = (((size_t)b * DIMc + k0) << 16) + px0;
#pragma unroll
        for (int it = 0; it < 2; it++) {
            int k = xk + it * 16;
            size_t off = xbase + ((size_t)k << 16) + xc8;
            unsigned dH = (unsigned)__cvta_generic_to_shared(
                sm + OFF_XH + s * XELEMS + k * XSTRIDE + xc8);
            unsigned dL = (unsigned)__cvta_generic_to_shared(
                sm + OFF_XL + s * XELEMS + k * XSTRIDE + xc8);
            CPA(dH, g_XH + off);
            CPA(dL, g_XL + off);
        }
#pragma unroll
        for (int it = 0; it < 2; it++) {
            int idx = tid + it * 256;
            if (idx < 384) {
                int oc = idx >> 2, k8 = (idx & 3) * 8;
                size_t off = (size_t)(oc0 + oc) * DIMc + k0 + k8;
                unsigned dH = (unsigned)__cvta_generic_to_shared(
                    sm + OFF_WH + s * WELEMS + oc * WSTRIDE + k8);
                unsigned dL = (unsigned)__cvta_generic_to_shared(
                    sm + OFF_WL + s * WELEMS + oc * WSTRIDE + k8);
                CPA(dH, g_WH + off);
                CPA(dL, g_WL + off);
            }
        }
    };

    float c[3][4][4];
#pragma unroll
    for (int mf = 0; mf < 3; mf++)
#pragma unroll
        for (int j = 0; j < 4; j++)
#pragma unroll
            for (int q = 0; q < 4; q++) c[mf][j][q] = 0.f;

    load_stage(0, 0);
    CPC();

#pragma unroll 1
    for (int kc = 0; kc < 6; kc++) {
        int cur = kc & 1;
        if (kc < 5) { load_stage(cur ^ 1, (kc + 1) * 32); CPC(); CPW1(); }
        else        { CPW0(); }
        __syncthreads();
        const __nv_bfloat16* xh = sm + OFF_XH + cur * XELEMS;
        const __nv_bfloat16* xl = sm + OFF_XL + cur * XELEMS;
        const __nv_bfloat16* wh = sm + OFF_WH + cur * WELEMS;
        const __nv_bfloat16* wl = sm + OFF_WL + cur * WELEMS;
#pragma unroll
        for (int ks = 0; ks < 2; ks++) {
            unsigned aH[3][4], aL[3][4], bH[2][4], bL[2][4];
#pragma unroll
            for (int mf = 0; mf < 3; mf++) {
                LDM_X4(aH[mf], (unsigned)__cvta_generic_to_shared(
                    wh + (m0 + mf * 16 + arow) * WSTRIDE + ks * 16 + acol8));
                LDM_X4(aL[mf], (unsigned)__cvta_generic_to_shared(
                    wl + (m0 + mf * 16 + arow) * WSTRIDE + ks * 16 + acol8));
            }
#pragma unroll
            for (int nb = 0; nb < 2; nb++) {
                LDM_X4T(bH[nb], (unsigned)__cvta_generic_to_shared(
                    xh + (ks * 16 + arow) * XSTRIDE + n0 + nb * 16 + acol8));
                LDM_X4T(bL[nb], (unsigned)__cvta_generic_to_shared(
                    xl + (ks * 16 + arow) * XSTRIDE + n0 + nb * 16 + acol8));
            }
#pragma unroll
            for (int mf = 0; mf < 3; mf++)
#pragma unroll
                for (int j = 0; j < 4; j++) {
                    unsigned bh0 = bH[j >> 1][(j & 1) * 2];
                    unsigned bh1 = bH[j >> 1][(j & 1) * 2 + 1];
                    unsigned bl0 = bL[j >> 1][(j & 1) * 2];
                    unsigned bl1 = bL[j >> 1][(j & 1) * 2 + 1];
                    MMA_BF16(c[mf][j], aH[mf], bh0, bh1);
                    MMA_BF16(c[mf][j], aH[mf], bl0, bl1);
                    MMA_BF16(c[mf][j], aL[mf], bh0, bh1);
                }
        }
        __syncthreads();
    }

#pragma unroll
    for (int mf = 0; mf < 3; mf++)
#pragma unroll
        for (int j = 0; j < 4; j++) {
            float v01 = fmaxf(c[mf][j][0], c[mf][j][1]);
            float v23 = fmaxf(c[mf][j][2], c[mf][j][3]);
            float p01 = fmaxf(v01, __shfl_xor_sync(0xffffffffu, v01, 1));
            float p23 = fmaxf(v23, __shfl_xor_sync(0xffffffffu, v23, 1));
            if (!(l & 1)) {
                int hp = wn * 8 + j * 2 + ((l & 2) >> 1);
                int rl = m0 + mf * 16 + (l >> 2);
                sPool[rl * 33 + hp] = p01;
                sPool[(rl + 8) * 33 + hp] = p23;
            }
        }
    __syncthreads();
#pragma unroll
    for (int it = 0; it < 12; it++) {
        int t = tid + it * 256;
        int ocl = t >> 5, hx = t & 31;
        g_P[((size_t)b * H3 + oc0 + ocl) * NPIX + y * HSp + cblk * 32 + hx] =
            sPool[ocl * 33 + hx];
    }
}

// ------------------------------------------------- depthwise 3x3 (SAME)
__global__ void __launch_bounds__(256) k_dw(const float* __restrict__ dww) {
    __shared__ float smh[18][132];
    int tid = threadIdx.x;
    int ch = blockIdx.y, b = blockIdx.z;
    int rg = blockIdx.x;
    int r0 = rg * 16;
    const float* src = g_P + ((size_t)b * H3 + ch) * NPIX;
    float*       dst = g_D + ((size_t)b * H3 + ch) * NPIX;
    float wgt[9];
#pragma unroll
    for (int i = 0; i < 9; i++) wgt[i] = dww[ch * 9 + i];

#pragma unroll
    for (int it = 0; it < 3; it++) {
        int idx = tid + it * 256;
        if (idx < 18 * 32) {
            int lr = idx >> 5, c4 = (idx & 31) * 4;
            int rr = r0 + lr - 1;
            float4 v = make_float4(0.f, 0.f, 0.f, 0.f);
            if (rr >= 0 && rr < 128)
                v = *(const float4*)(src + rr * 128 + c4);
            smh[lr][1 + c4] = v.x; smh[lr][2 + c4] = v.y;
            smh[lr][3 + c4] = v.z; smh[lr][4 + c4] = v.w;
            if (c4 == 0)  smh[lr][0] = 0.f;
            if (c4 == 124) smh[lr][129] = 0.f;
        }
    }
    __syncthreads();

    float ss = 0.f;
#pragma unroll
    for (int it = 0; it < 8; it++) {
        int p = tid + it * 256;
        int r = p >> 7, cc = p & 127;
        float s = 0.f;
#pragma unroll
        for (int dr = 0; dr < 3; dr++)
#pragma unroll
            for (int dc = 0; dc < 3; dc++)
                s = fmaf(wgt[dr * 3 + dc], smh[r + dr][cc + dc], s);
        dst[r0 * 128 + p] = s;
        ss = fmaf(s, s, ss);
    }
    if (ch < 2 * DIMc) {
#pragma unroll
        for (int o = 16; o > 0; o >>= 1) ss += __shfl_xor_sync(0xffffffffu, ss, o);
        __shared__ float red[8];
        if ((tid & 31) == 0) red[tid >> 5] = ss;
        __syncthreads();
        if (tid < 8) {
            float v = red[tid];
#pragma unroll
            for (int o = 4; o > 0; o >>= 1) v += __shfl_xor_sync(0xffu, v, o);
            if (tid == 0) atomicAdd(&g_normsq[b * 2 * DIMc + ch], v);
        }
    }
}

// ----------------------------------------- attn[b,h,c,d] = sum_n q k
__global__ void __launch_bounds__(256) k_attn() {
    __shared__ float qs[32][65];
    __shared__ float ks[32][65];
    int tid = threadIdx.x;
    int bh = blockIdx.y;
    int b = bh / HEADS, h = bh - b * HEADS;
    int n0 = blockIdx.x * 1024;
    const float* qb = g_D + ((size_t)b * H3 + h * CPH) * NPIX;
    const float* kb = g_D + ((size_t)b * H3 + DIMc + h * CPH) * NPIX;
    int dgi = tid & 7, cg = (tid >> 3) & 7, sl = tid >> 6;
    float acc[4][4];
#pragma unroll
    for (int i = 0; i < 4; i++)
#pragma unroll
        for (int j = 0; j < 4; j++) acc[i][j] = 0.f;

    for (int t = 0; t < 16; t++) {
        int n = n0 + t * 64;
#pragma unroll
        for (int it = 0; it < 2; it++) {
            int idx = tid + it * 256;
            int row = idx >> 4, n4 = (idx & 15) * 4;
            float4 q4 = *(const float4*)(qb + (size_t)row * NPIX + n + n4);
            float4 k4 = *(const float4*)(kb + (size_t)row * NPIX + n + n4);
            qs[row][n4 + 0] = q4.x; qs[row][n4 + 1] = q4.y;
            qs[row][n4 + 2] = q4.z; qs[row][n4 + 3] = q4.w;
            ks[row][n4 + 0] = k4.x; ks[row][n4 + 1] = k4.y;
            ks[row][n4 + 2] = k4.z; ks[row][n4 + 3] = k4.w;
        }
        __syncthreads();
#pragma unroll
        for (int nn = sl * 16; nn < sl * 16 + 16; nn++) {
            float qv[4], kv[4];
#pragma unroll
            for (int i = 0; i < 4; i++) qv[i] = qs[cg * 4 + i][nn];
#pragma unroll
            for (int j = 0; j < 4; j++) kv[j] = ks[dgi * 4 + j][nn];
#pragma unroll
            for (int i = 0; i < 4; i++)
#pragma unroll
                for (int j = 0; j < 4; j++)
                    acc[i][j] = fmaf(qv[i], kv[j], acc[i][j]);
        }
        __syncthreads();
    }
#pragma unroll
    for (int i = 0; i < 4; i++)
#pragma unroll
        for (int j = 0; j < 4; j++)
            atomicAdd(&g_attn[((size_t)bh * CPH + cg * 4 + i) * CPH + dgi * 4 + j],
                      acc[i][j]);
}

// --------------- normalize, temperature, 4x top-k masked softmax, combine
__global__ void __launch_bounds__(256) k_soft(const float* __restrict__ temp,
                                              const float* __restrict__ a1,
                                              const float* __restrict__ a2,
                                              const float* __restrict__ a3,
                                              const float* __restrict__ a4) {
    int lane = threadIdx.x & 31;
    int wid = blockIdx.x * 8 + (threadIdx.x >> 5);
    int bh = wid >> 5, c = wid & 31;
    int b = bh / HEADS, h = bh - b * HEADS;
    float v = g_attn[((size_t)bh * CPH + c) * CPH + lane];
    float nq = fmaxf(sqrtf(g_normsq[b * 2 * DIMc + h * CPH + c]), 1e-12f);
    float nk = fmaxf(sqrtf(g_normsq[b * 2 * DIMc + DIMc + h * CPH + lane]), 1e-12f);
    v = v / (nq * nk) * temp[h];
    int rank = 0;
#pragma unroll
    for (int j = 0; j < 32; j++) {
        float vj = __shfl_sync(0xffffffffu, v, j);
        rank += (vj > v || (vj == v && j < lane)) ? 1 : 0;
    }
    float m = v;
#pragma unroll
    for (int o = 16; o > 0; o >>= 1) m = fmaxf(m, __shfl_xor_sync(0xffffffffu, m, o));
    float e = expf(v - m);
    float e16 = rank < 16 ? e : 0.f;
    float e21 = rank < 21 ? e : 0.f;
    float e24 = rank < 24 ? e : 0.f;
    float e25 = rank < 25 ? e : 0.f;
    float s16 = e16, s21 = e21, s24 = e24, s25 = e25;
#pragma unroll
    for (int o = 16; o > 0; o >>= 1) {
        s16 += __shfl_xor_sync(0xffffffffu, s16, o);
        s21 += __shfl_xor_sync(0xffffffffu, s21, o);
        s24 += __shfl_xor_sync(0xffffffffu, s24, o);
        s25 += __shfl_xor_sync(0xffffffffu, s25, o);
    }
    float r = e16 * (a1[0] / s16) + e21 * (a2[0] / s21) +
              e24 * (a3[0] / s24) + e25 * (a4[0] / s25);
    g_A[((size_t)bh * CPH + c) * CPH + lane] = r;
}

// ------------------- out = gelu(A @ v), written as bf16 hi/lo for proj
__global__ void __launch_bounds__(256) k_av() {
    __shared__ float sA[1024];
    int tid = threadIdx.x;
    int bh = blockIdx.y;
    int b = bh / HEADS, h = bh - b * HEADS;
#pragma unroll
    for (int it = 0; it < 4; it++)
        sA[tid + it * 256] = g_A[(size_t)bh * 1024 + tid + it * 256];
    __syncthreads();
    int n = blockIdx.x * 256 + tid;
    const float* vb = g_D + ((size_t)b * H3 + 2 * DIMc + h * CPH) * NPIX + n;
    u64 vp[16];
#pragma unroll
    for (int d = 0; d < 16; d++) {
        float v0 = vb[(size_t)(2 * d) * NPIX];
        float v1 = vb[(size_t)(2 * d + 1) * NPIX];
        PACK2(vp[d], v0, v1);
    }
    size_t ob = ((size_t)b * DIMc + h * CPH) * NPIX + n;
#pragma unroll
    for (int c2 = 0; c2 < 32; c2++) {
        u64 acc = 0ull;
        const u64* ap = (const u64*)(&sA[c2 * 32]);
#pragma unroll
        for (int d = 0; d < 16; d++)
            FMA2(acc, ap[d], vp[d]);
        float lo, hi;
        UNPACK2(lo, hi, acc);
        float s = lo + hi;
        s = s * normcdff(s);
        __nv_bfloat16 hh = __float2bfloat16(s);
        g_OH[ob + (size_t)c2 * NPIX] = hh;
        g_OL[ob + (size_t)c2 * NPIX] = __float2bfloat16(s - __bfloat162float(hh));
    }
}

// -------------------- proj 1x1, pipelined HMMA, upsample-fused epilogue
__global__ void __launch_bounds__(256) k_proj(float* __restrict__ out) {
    extern __shared__ __nv_bfloat16 sm[];

    int tid = threadIdx.x;
    int b = blockIdx.z;
    int oc0 = blockIdx.y * 96;
    int n0 = blockIdx.x * 128;
    int hy = blockIdx.x;

    int wid = tid >> 5, l = tid & 31;
    int wm = wid & 1, wn = wid >> 1;
    int m0 = wm * 48, nw0 = wn * 32;
    int arow = (l & 7) + ((l >> 3) & 1) * 8;
    int acol8 = (l >> 4) * 8;

    int xk = tid >> 4, xc8 = (tid & 15) * 8;

    auto load_stage = [&](int s, int k0) {
#pragma unroll
        for (int it = 0; it < 2; it++) {
            int k = xk + it * 16;
            size_t off = ((size_t)b * DIMc + k0 + k) * NPIX + n0 + xc8;
            unsigned dH = (unsigned)__cvta_generic_to_shared(
                sm + OFF_XH + s * XELEMS + k * XSTRIDE + xc8);
            unsigned dL = (unsigned)__cvta_generic_to_shared(
                sm + OFF_XL + s * XELEMS + k * XSTRIDE + xc8);
            CPA(dH, g_OH + off);
            CPA(dL, g_OL + off);
        }
#pragma unroll
        for (int it = 0; it < 2; it++) {
            int idx = tid + it * 256;
            if (idx < 384) {
                int oc = idx >> 2, k8 = (idx & 3) * 8;
                size_t off = (size_t)(oc0 + oc) * DIMc + k0 + k8;
                unsigned dH = (unsigned)__cvta_generic_to_shared(
                    sm + OFF_WH + s * WELEMS + oc * WSTRIDE + k8);
                unsigned dL = (unsigned)__cvta_generic_to_shared(
                    sm + OFF_WL + s * WELEMS + oc * WSTRIDE + k8);
                CPA(dH, g_PWH + off);
                CPA(dL, g_PWL + off);
            }
        }
    };

    float c[3][4][4];
#pragma unroll
    for (int mf = 0; mf < 3; mf++)
#pragma unroll
        for (int j = 0; j < 4; j++)
#pragma unroll
            for (int q = 0; q < 4; q++) c[mf][j][q] = 0.f;

    load_stage(0, 0);
    CPC();

#pragma unroll 1
    for (int kc = 0; kc < 6; kc++) {
        int cur = kc & 1;
        if (kc < 5) { load_stage(cur ^ 1, (kc + 1) * 32); CPC(); CPW1(); }
        else        { CPW0(); }
        __syncthreads();
        const __nv_bfloat16* xh = sm + OFF_XH + cur * XELEMS;
        const __nv_bfloat16* xl = sm + OFF_XL + cur * XELEMS;
        const __nv_bfloat16* wh = sm + OFF_WH + cur * WELEMS;
        const __nv_bfloat16* wl = sm + OFF_WL + cur * WELEMS;
#pragma unroll
        for (int ks = 0; ks < 2; ks++) {
            unsigned aH[3][4], aL[3][4], bH[2][4], bL[2][4];
#pragma unroll
            for (int mf = 0; mf < 3; mf++) {
                LDM_X4(aH[mf], (unsigned)__cvta_generic_to_shared(
                    wh + (m0 + mf * 16 + arow) * WSTRIDE + ks * 16 + acol8));
                LDM_X4(aL[mf], (unsigned)__cvta_generic_to_shared(
                    wl + (m0 + mf * 16 + arow) * WSTRIDE + ks * 16 + acol8));
            }
#pragma unroll
            for (int nb = 0; nb < 2; nb++) {
                LDM_X4T(bH[nb], (unsigned)__cvta_generic_to_shared(
                    xh + (ks * 16 + arow) * XSTRIDE + nw0 + nb * 16 + acol8));
                LDM_X4T(bL[nb], (unsigned)__cvta_generic_to_shared(
                    xl + (ks * 16 + arow) * XSTRIDE + nw0 + nb * 16 + acol8));
            }
#pragma unroll
            for (int mf = 0; mf < 3; mf++)
#pragma unroll
                for (int j = 0; j < 4; j++) {
                    unsigned bh0 = bH[j >> 1][(j & 1) * 2];
                    unsigned bh1 = bH[j >> 1][(j & 1) * 2 + 1];
                    unsigned bl0 = bL[j >> 1][(j & 1) * 2];
                    unsigned bl1 = bL[j >> 1][(j & 1) * 2 + 1];
                    MMA_BF16(c[mf][j], aH[mf], bh0, bh1);
                    MMA_BF16(c[mf][j], aH[mf], bl0, bl1);
                    MMA_BF16(c[mf][j], aL[mf], bh0, bh1);
                }
        }
        __syncthreads();
    }

    int fr0 = 2 * hy;
#pragma unroll
    for (int mf = 0; mf < 3; mf++)
#pragma unroll
        for (int j = 0; j < 4; j++)
#pragma unroll
            for (int rh = 0; rh < 2; rh++) {
                float v0 = c[mf][j][rh * 2 + 0];
                float v1 = c[mf][j][rh * 2 + 1];
                int oc = oc0 + m0 + mf * 16 + (l >> 2) + 8 * rh;
                int hc = nw0 + (j >> 1) * 16 + (j & 1) * 8 + 2 * (l & 3);
                float4 v4 = make_float4(v0, v0, v1, v1);
                float* ob = out + ((size_t)b * DIMc + oc) * 65536 +
                            fr0 * 256 + 2 * hc;
                *(float4*)ob = v4;
                *(float4*)(ob + 256) = v4;
            }
}

// ---------------------------------------------------------------- launch
extern "C" void kernel_launch(void* const* d_in, const int* in_sizes, int n_in,
                              void* d_out, int out_size) {
    const float* x      = (const float*)d_in[0];
    const float* temp   = (const float*)d_in[1];
    const float* qkv_w  = (const float*)d_in[2];
    const float* dw_w   = (const float*)d_in[3];
    const float* proj_w = (const float*)d_in[4];
    const float* a1 = (const float*)d_in[5];
    const float* a2 = (const float*)d_in[6];
    const float* a3 = (const float*)d_in[7];
    const float* a4 = (const float*)d_in[8];
    float* out = (float*)d_out;

    cudaFuncSetAttribute(k_qkvpool, cudaFuncAttributeMaxDynamicSharedMemorySize,
                         SMEM_QKV_BYTES);
    cudaFuncSetAttribute(k_proj, cudaFuncAttributeMaxDynamicSharedMemorySize,
                         SMEM_PROJ_BYTES);

    k_zero<<<96, 256>>>();
    k_splitX<<<Bn * DIMc, 256>>>(x);
    k_splitW<<<432, 256>>>(qkv_w, proj_w);
    k_qkvpool<<<dim3(6, 512, 4), 256, SMEM_QKV_BYTES>>>();
    k_dw<<<dim3(8, 576, 4), 256>>>(dw_w);
    k_attn<<<dim3(16, 24), 256>>>();
    k_soft<<<96, 256>>>(temp, a1, a2, a3, a4);
    k_av<<<dim3(64, 24), 256>>>();
    k_proj<<<dim3(128, 2, 4), 256, SMEM_PROJ_BYTES>>>(out);
}